// round 2
// baseline (speedup 1.0000x reference)
#include <cuda_runtime.h>
#include <math.h>

#define NNODES 50000
#define NADJ   6
#define NEDGE  800000
#define NH     256
#define LN_EPS 1e-5f

// ---------------- device scratch (no allocations allowed) ----------------
static __device__ float g_state0[(size_t)NNODES * NH];
static __device__ float g_state1[(size_t)NNODES * NH];
static __device__ float g_state2[(size_t)NNODES * NH];
static __device__ int   g_cnt[NADJ * NNODES];
static __device__ int   g_rowptr[NADJ * (NNODES + 1)];
static __device__ int   g_cur[NADJ * NNODES];
static __device__ int   g_ecol[(size_t)NADJ * NEDGE];
static __device__ float g_eval[(size_t)NADJ * NEDGE];
static __device__ int   g_adj_idx[6];   // [seq0,seq1,seq2,res0,res1,res2]

// ---------------- idx decode: int32 vs int64 autodetect -------------------
__global__ void decode_idx_kernel(const int* __restrict__ seq_raw,
                                  const int* __restrict__ res_raw) {
    if (threadIdx.x != 0 || blockIdx.x != 0) return;
    long long a[6];
    int b[6];
    bool v64 = true, v32 = true;
    const long long* s64 = (const long long*)seq_raw;
    const long long* r64 = (const long long*)res_raw;
#pragma unroll
    for (int i = 0; i < 3; i++) {
        long long t = s64[i]; a[i] = t;     if (t < 0 || t >= NADJ) v64 = false;
        long long u = r64[i]; a[3 + i] = u; if (u < 0 || u >= NADJ) v64 = false;
        int p = seq_raw[i]; b[i] = p;       if (p < 0 || p >= NADJ) v32 = false;
        int q = res_raw[i]; b[3 + i] = q;   if (q < 0 || q >= NADJ) v32 = false;
    }
    (void)v32;
#pragma unroll
    for (int i = 0; i < 6; i++)
        g_adj_idx[i] = v64 ? (int)a[i] : b[i];
}

// ---------------- CSR build --------------------------------------------
__global__ void zero_cnt_kernel() {
    int i = blockIdx.x * blockDim.x + threadIdx.x;
    if (i < NADJ * NNODES) g_cnt[i] = 0;
}

__global__ void hist_kernel(const int* __restrict__ rows) {
    int i = blockIdx.x * blockDim.x + threadIdx.x;
    if (i >= NADJ * NEDGE) return;
    int adj = i / NEDGE;
    int r = rows[i];
    atomicAdd(&g_cnt[adj * NNODES + r], 1);
}

__global__ void scan_kernel() {
    // one block (1024 threads) per adjacency: exclusive scan of 50000 counts
    __shared__ int s[1024];
    int a = blockIdx.x;
    int t = threadIdx.x;
    int carry = 0;
    for (int base = 0; base < NNODES; base += 1024) {
        int i = base + t;
        int v = (i < NNODES) ? g_cnt[a * NNODES + i] : 0;
        s[t] = v;
        __syncthreads();
        for (int off = 1; off < 1024; off <<= 1) {
            int u = (t >= off) ? s[t - off] : 0;
            __syncthreads();
            s[t] += u;
            __syncthreads();
        }
        int ex = s[t] - v;
        if (i < NNODES) {
            int val = carry + ex;
            g_rowptr[a * (NNODES + 1) + i] = val;
            g_cur[a * NNODES + i] = val;
        }
        carry += s[1023];
        __syncthreads();
    }
    if (t == 0) g_rowptr[a * (NNODES + 1) + NNODES] = carry;
}

__global__ void scatter_kernel(const int* __restrict__ rows,
                               const int* __restrict__ cols,
                               const float* __restrict__ vals) {
    int i = blockIdx.x * blockDim.x + threadIdx.x;
    if (i >= NADJ * NEDGE) return;
    int adj = i / NEDGE;
    int r = rows[i];
    int pos = atomicAdd(&g_cur[adj * NNODES + r], 1);
    g_ecol[(size_t)adj * NEDGE + pos] = cols[i];
    g_eval[(size_t)adj * NEDGE + pos] = vals[i];
}

// ---------------- GEMM: h = x @ W^T + b  (M=50000, N=K=256, fp32) --------
__global__ __launch_bounds__(256) void gemm_kernel(const float* __restrict__ A,
                                                   const float* __restrict__ W,
                                                   const float* __restrict__ bias,
                                                   float* __restrict__ C) {
    const int BM = 128, BN = 128, BK = 16;
    __shared__ float As[BK][BM];
    __shared__ float Bs[BK][BN];
    int t = threadIdx.x;
    int m0 = blockIdx.x * BM;
    int n0 = blockIdx.y * BN;
    int tx = t & 15;
    int ty = t >> 4;
    float acc[8][8];
#pragma unroll
    for (int i = 0; i < 8; i++)
#pragma unroll
        for (int j = 0; j < 8; j++) acc[i][j] = 0.f;

    for (int k0 = 0; k0 < NH; k0 += BK) {
        // A tile: 128x16 = 512 float4s; each thread loads 2
#pragma unroll
        for (int L = 0; L < 2; L++) {
            int f = t + L * 256;
            int row = f >> 2;
            int c4 = f & 3;
            float4 av = make_float4(0.f, 0.f, 0.f, 0.f);
            int gm = m0 + row;
            if (gm < NNODES)
                av = *(const float4*)(A + (size_t)gm * NH + k0 + c4 * 4);
            As[c4 * 4 + 0][row] = av.x;
            As[c4 * 4 + 1][row] = av.y;
            As[c4 * 4 + 2][row] = av.z;
            As[c4 * 4 + 3][row] = av.w;
        }
        // B tile: Bs[k][n] = W[n0+n][k0+k]
        {
            int n = t >> 1;
            int kb = (t & 1) * 8;
            const float* wp = W + (size_t)(n0 + n) * NH + k0 + kb;
            float4 w0 = *(const float4*)(wp);
            float4 w1 = *(const float4*)(wp + 4);
            Bs[kb + 0][n] = w0.x; Bs[kb + 1][n] = w0.y;
            Bs[kb + 2][n] = w0.z; Bs[kb + 3][n] = w0.w;
            Bs[kb + 4][n] = w1.x; Bs[kb + 5][n] = w1.y;
            Bs[kb + 6][n] = w1.z; Bs[kb + 7][n] = w1.w;
        }
        __syncthreads();
#pragma unroll
        for (int k = 0; k < BK; k++) {
            float ar[8], br[8];
#pragma unroll
            for (int i = 0; i < 8; i++) ar[i] = As[k][ty * 8 + i];
#pragma unroll
            for (int j = 0; j < 8; j++) br[j] = Bs[k][tx * 8 + j];
#pragma unroll
            for (int i = 0; i < 8; i++)
#pragma unroll
                for (int j = 0; j < 8; j++) acc[i][j] += ar[i] * br[j];
        }
        __syncthreads();
    }
#pragma unroll
    for (int i = 0; i < 8; i++) {
        int gm = m0 + ty * 8 + i;
        if (gm >= NNODES) break;
#pragma unroll
        for (int j = 0; j < 8; j += 4) {
            int gn = n0 + tx * 8 + j;
            float4 bv = *(const float4*)(bias + gn);
            float4 o;
            o.x = acc[i][j + 0] + bv.x;
            o.y = acc[i][j + 1] + bv.y;
            o.z = acc[i][j + 2] + bv.z;
            o.w = acc[i][j + 3] + bv.w;
            *(float4*)(C + (size_t)gm * NH + gn) = o;
        }
    }
}

// ---------------- CSR SpMM: warp-per-row, register accumulators ----------
template <int NSRC>
__global__ __launch_bounds__(256) void spmm_kernel(const float* __restrict__ s0, int sel0,
                                                   const float* __restrict__ s1, int sel1,
                                                   const float* __restrict__ s2, int sel2,
                                                   float* __restrict__ dst) {
    int w = (blockIdx.x * blockDim.x + threadIdx.x) >> 5;
    int lane = threadIdx.x & 31;
    if (w >= NNODES) return;
    float4 a0 = make_float4(0.f, 0.f, 0.f, 0.f);
    float4 a1 = make_float4(0.f, 0.f, 0.f, 0.f);
    const float* srcs[3] = {s0, s1, s2};
    const int sels[3] = {sel0, sel1, sel2};
#pragma unroll
    for (int s = 0; s < NSRC; s++) {
        int adj = g_adj_idx[sels[s]];
        const int* rp = g_rowptr + adj * (NNODES + 1);
        int beg = __ldg(rp + w), end = __ldg(rp + w + 1);
        const int* ec = g_ecol + (size_t)adj * NEDGE;
        const float* ev = g_eval + (size_t)adj * NEDGE;
        const float* src = srcs[s];
        int c = 0;
        float v = 0.f;
        if (beg < end) { c = __ldg(ec + beg); v = __ldg(ev + beg); }
        for (int e = beg; e < end; e++) {
            int cn = 0;
            float vn = 0.f;
            if (e + 1 < end) { cn = __ldg(ec + e + 1); vn = __ldg(ev + e + 1); }
            const float4* row = (const float4*)(src + (size_t)c * NH);
            float4 p = __ldg(row + lane);
            float4 q = __ldg(row + lane + 32);
            a0.x += v * p.x; a0.y += v * p.y; a0.z += v * p.z; a0.w += v * p.w;
            a1.x += v * q.x; a1.y += v * q.y; a1.z += v * q.z; a1.w += v * q.w;
            c = cn; v = vn;
        }
    }
    float4* drow = (float4*)(dst + (size_t)w * NH);
    drow[lane] = a0;
    drow[lane + 32] = a1;
}

// ---------------- fused step-3 SpMM + LayerNorm + exact GELU -------------
__global__ __launch_bounds__(256) void spmm_ln_gelu_kernel(
    const float* __restrict__ s0, int sel0,
    const float* __restrict__ s1, int sel1,
    const float* __restrict__ s2, int sel2,
    const float* __restrict__ gamma, const float* __restrict__ beta,
    float* __restrict__ out) {
    int w = (blockIdx.x * blockDim.x + threadIdx.x) >> 5;
    int lane = threadIdx.x & 31;
    if (w >= NNODES) return;
    float4 a0 = make_float4(0.f, 0.f, 0.f, 0.f);
    float4 a1 = make_float4(0.f, 0.f, 0.f, 0.f);
    const float* srcs[3] = {s0, s1, s2};
    const int sels[3] = {sel0, sel1, sel2};
#pragma unroll
    for (int s = 0; s < 3; s++) {
        int adj = g_adj_idx[sels[s]];
        const int* rp = g_rowptr + adj * (NNODES + 1);
        int beg = __ldg(rp + w), end = __ldg(rp + w + 1);
        const int* ec = g_ecol + (size_t)adj * NEDGE;
        const float* ev = g_eval + (size_t)adj * NEDGE;
        const float* src = srcs[s];
        int c = 0;
        float v = 0.f;
        if (beg < end) { c = __ldg(ec + beg); v = __ldg(ev + beg); }
        for (int e = beg; e < end; e++) {
            int cn = 0;
            float vn = 0.f;
            if (e + 1 < end) { cn = __ldg(ec + e + 1); vn = __ldg(ev + e + 1); }
            const float4* row = (const float4*)(src + (size_t)c * NH);
            float4 p = __ldg(row + lane);
            float4 q = __ldg(row + lane + 32);
            a0.x += v * p.x; a0.y += v * p.y; a0.z += v * p.z; a0.w += v * p.w;
            a1.x += v * q.x; a1.y += v * q.y; a1.z += v * q.z; a1.w += v * q.w;
            c = cn; v = vn;
        }
    }
    // LayerNorm over 256 elems held by the warp (8 per lane)
    float sum = a0.x + a0.y + a0.z + a0.w + a1.x + a1.y + a1.z + a1.w;
    float sq = a0.x * a0.x + a0.y * a0.y + a0.z * a0.z + a0.w * a0.w +
               a1.x * a1.x + a1.y * a1.y + a1.z * a1.z + a1.w * a1.w;
#pragma unroll
    for (int off = 16; off >= 1; off >>= 1) {
        sum += __shfl_xor_sync(0xFFFFFFFFu, sum, off);
        sq  += __shfl_xor_sync(0xFFFFFFFFu, sq, off);
    }
    float mean = sum * (1.f / NH);
    float var = sq * (1.f / NH) - mean * mean;
    float inv = rsqrtf(var + LN_EPS);

    float4 g0 = __ldg((const float4*)gamma + lane);
    float4 g1 = __ldg((const float4*)gamma + lane + 32);
    float4 b0 = __ldg((const float4*)beta + lane);
    float4 b1 = __ldg((const float4*)beta + lane + 32);

    float xs[8] = {a0.x, a0.y, a0.z, a0.w, a1.x, a1.y, a1.z, a1.w};
    float gs[8] = {g0.x, g0.y, g0.z, g0.w, g1.x, g1.y, g1.z, g1.w};
    float bs[8] = {b0.x, b0.y, b0.z, b0.w, b1.x, b1.y, b1.z, b1.w};
    float r[8];
#pragma unroll
    for (int i = 0; i < 8; i++) {
        float y = (xs[i] - mean) * inv * gs[i] + bs[i];
        r[i] = 0.5f * y * (1.f + erff(y * 0.70710678118654752f));
    }
    float4* orow = (float4*)(out + (size_t)w * NH);
    orow[lane] = make_float4(r[0], r[1], r[2], r[3]);
    orow[lane + 32] = make_float4(r[4], r[5], r[6], r[7]);
}

// ---------------- launch ---------------------------------------------
extern "C" void kernel_launch(void* const* d_in, const int* in_sizes, int n_in,
                              void* d_out, int out_size) {
    const float* x    = (const float*)d_in[0];
    const int* rows   = (const int*)d_in[1];
    const int* cols   = (const int*)d_in[2];
    const float* vals = (const float*)d_in[3];
    const int* seqr   = (const int*)d_in[4];
    const int* resr   = (const int*)d_in[5];
    const float* W    = (const float*)d_in[6];
    const float* b    = (const float*)d_in[7];
    const float* gamma = (const float*)d_in[8];
    const float* beta  = (const float*)d_in[9];
    float* out = (float*)d_out;

    static float *s0 = nullptr, *s1 = nullptr, *s2 = nullptr;
    if (!s0) {
        cudaGetSymbolAddress((void**)&s0, g_state0);
        cudaGetSymbolAddress((void**)&s1, g_state1);
        cudaGetSymbolAddress((void**)&s2, g_state2);
    }

    decode_idx_kernel<<<1, 1>>>(seqr, resr);
    zero_cnt_kernel<<<(NADJ * NNODES + 255) / 256, 256>>>();
    hist_kernel<<<(NADJ * NEDGE + 255) / 256, 256>>>(rows);
    scan_kernel<<<NADJ, 1024>>>();
    scatter_kernel<<<(NADJ * NEDGE + 255) / 256, 256>>>(rows, cols, vals);

    gemm_kernel<<<dim3((NNODES + 127) / 128, NH / 128), 256>>>(x, W, b, s0);

    const int spmm_blocks = (NNODES + 7) / 8;  // warp per row, 8 warps/block
    spmm_kernel<1><<<spmm_blocks, 256>>>(s0, 0, nullptr, 0, nullptr, 0, s1);
    spmm_kernel<2><<<spmm_blocks, 256>>>(s1, 1, s0, 3, nullptr, 0, s2);
    spmm_ln_gelu_kernel<<<spmm_blocks, 256>>>(s2, 2, s0, 4, s1, 5, gamma, beta, out);
}

// round 3
// speedup vs baseline: 1.1343x; 1.1343x over previous
#include <cuda_runtime.h>
#include <math.h>

#define NNODES 50000
#define NADJ   6
#define NEDGE  800000
#define NH     256
#define LN_EPS 1e-5f

#define SCAN_B 1024
#define BLK_PER_ADJ ((NNODES + SCAN_B - 1) / SCAN_B)   // 49

// ---------------- device scratch (no allocations allowed) ----------------
static __device__ float g_state0[(size_t)NNODES * NH];
static __device__ float g_state1[(size_t)NNODES * NH];
static __device__ float g_state2[(size_t)NNODES * NH];
static __device__ int   g_cnt[NADJ * NNODES];
static __device__ int   g_rowptr[NADJ * (NNODES + 1)];
static __device__ int   g_cur[NADJ * NNODES];
static __device__ int   g_blksum[NADJ * BLK_PER_ADJ];
static __device__ int   g_ecol[(size_t)NADJ * NEDGE];
static __device__ float g_eval[(size_t)NADJ * NEDGE];
static __device__ int   g_adj_idx[6];   // [seq0,seq1,seq2,res0,res1,res2]
static __device__ int   g_used[NADJ];

// ---------------- idx decode: int32 vs int64 autodetect -------------------
__global__ void decode_idx_kernel(const int* __restrict__ seq_raw,
                                  const int* __restrict__ res_raw) {
    if (threadIdx.x != 0 || blockIdx.x != 0) return;
    long long a[6];
    int b[6];
    bool v64 = true, v32 = true;
    const long long* s64 = (const long long*)seq_raw;
    const long long* r64 = (const long long*)res_raw;
#pragma unroll
    for (int i = 0; i < 3; i++) {
        long long t = s64[i]; a[i] = t;     if (t < 0 || t >= NADJ) v64 = false;
        long long u = r64[i]; a[3 + i] = u; if (u < 0 || u >= NADJ) v64 = false;
        int p = seq_raw[i]; b[i] = p;       if (p < 0 || p >= NADJ) v32 = false;
        int q = res_raw[i]; b[3 + i] = q;   if (q < 0 || q >= NADJ) v32 = false;
    }
    (void)v32;
#pragma unroll
    for (int i = 0; i < NADJ; i++) g_used[i] = 0;
#pragma unroll
    for (int i = 0; i < 6; i++) {
        int v = v64 ? (int)a[i] : b[i];
        g_adj_idx[i] = v;
        g_used[v] = 1;
    }
}

// ---------------- CSR build --------------------------------------------
__global__ void zero_cnt_kernel() {
    int i = blockIdx.x * blockDim.x + threadIdx.x;
    if (i < NADJ * NNODES) g_cnt[i] = 0;
}

__global__ void hist_kernel(const int* __restrict__ rows) {
    int i = blockIdx.x * blockDim.x + threadIdx.x;
    if (i >= NADJ * NEDGE) return;
    int adj = i / NEDGE;
    if (!g_used[adj]) return;
    int r = rows[i];
    atomicAdd(&g_cnt[adj * NNODES + r], 1);
}

// Phase A: per-block inclusive scan of 1024-elem chunks; write exclusive
// value back in place and block total to g_blksum. Grid = NADJ*BLK_PER_ADJ.
__global__ __launch_bounds__(SCAN_B) void scanA_kernel() {
    __shared__ int s[SCAN_B];
    int bx = blockIdx.x;
    int adj = bx / BLK_PER_ADJ;
    int blk = bx % BLK_PER_ADJ;
    int t = threadIdx.x;
    int i = blk * SCAN_B + t;
    int v = (i < NNODES) ? g_cnt[adj * NNODES + i] : 0;
    s[t] = v;
    __syncthreads();
#pragma unroll
    for (int off = 1; off < SCAN_B; off <<= 1) {
        int u = (t >= off) ? s[t - off] : 0;
        __syncthreads();
        s[t] += u;
        __syncthreads();
    }
    if (i < NNODES) g_cnt[adj * NNODES + i] = s[t] - v;   // exclusive within block
    if (t == SCAN_B - 1) g_blksum[adj * BLK_PER_ADJ + blk] = s[t];
}

// Phase B: exclusive-scan the 49 block sums per adjacency (tiny). 1 block.
__global__ __launch_bounds__(512) void scanB_kernel() {
    __shared__ int sb[NADJ * BLK_PER_ADJ];
    int t = threadIdx.x;
    for (int i = t; i < NADJ * BLK_PER_ADJ; i += blockDim.x) sb[i] = g_blksum[i];
    __syncthreads();
    if (t < NADJ) {
        int run = 0;
        for (int k = 0; k < BLK_PER_ADJ; k++) {
            int v = sb[t * BLK_PER_ADJ + k];
            sb[t * BLK_PER_ADJ + k] = run;
            run += v;
        }
        g_rowptr[t * (NNODES + 1) + NNODES] = run;
    }
    __syncthreads();
    for (int i = t; i < NADJ * BLK_PER_ADJ; i += blockDim.x) g_blksum[i] = sb[i];
}

// Phase C: add block offsets, produce final rowptr + cursor.
__global__ __launch_bounds__(SCAN_B) void scanC_kernel() {
    int bx = blockIdx.x;
    int adj = bx / BLK_PER_ADJ;
    int blk = bx % BLK_PER_ADJ;
    int t = threadIdx.x;
    int i = blk * SCAN_B + t;
    if (i >= NNODES) return;
    int val = g_cnt[adj * NNODES + i] + g_blksum[adj * BLK_PER_ADJ + blk];
    g_rowptr[adj * (NNODES + 1) + i] = val;
    g_cur[adj * NNODES + i] = val;
}

__global__ void scatter_kernel(const int* __restrict__ rows,
                               const int* __restrict__ cols,
                               const float* __restrict__ vals) {
    int i = blockIdx.x * blockDim.x + threadIdx.x;
    if (i >= NADJ * NEDGE) return;
    int adj = i / NEDGE;
    if (!g_used[adj]) return;
    int r = rows[i];
    int pos = atomicAdd(&g_cur[adj * NNODES + r], 1);
    g_ecol[(size_t)adj * NEDGE + pos] = cols[i];
    g_eval[(size_t)adj * NEDGE + pos] = vals[i];
}

// ---------------- GEMM: h = x @ W^T + b  (M=50000, N=K=256, fp32) --------
__global__ __launch_bounds__(256) void gemm_kernel(const float* __restrict__ A,
                                                   const float* __restrict__ W,
                                                   const float* __restrict__ bias,
                                                   float* __restrict__ C) {
    const int BM = 128, BN = 128, BK = 16;
    __shared__ float As[BK][BM];
    __shared__ float Bs[BK][BN];
    int t = threadIdx.x;
    int m0 = blockIdx.x * BM;
    int n0 = blockIdx.y * BN;
    int tx = t & 15;
    int ty = t >> 4;
    float acc[8][8];
#pragma unroll
    for (int i = 0; i < 8; i++)
#pragma unroll
        for (int j = 0; j < 8; j++) acc[i][j] = 0.f;

    for (int k0 = 0; k0 < NH; k0 += BK) {
#pragma unroll
        for (int L = 0; L < 2; L++) {
            int f = t + L * 256;
            int row = f >> 2;
            int c4 = f & 3;
            float4 av = make_float4(0.f, 0.f, 0.f, 0.f);
            int gm = m0 + row;
            if (gm < NNODES)
                av = *(const float4*)(A + (size_t)gm * NH + k0 + c4 * 4);
            As[c4 * 4 + 0][row] = av.x;
            As[c4 * 4 + 1][row] = av.y;
            As[c4 * 4 + 2][row] = av.z;
            As[c4 * 4 + 3][row] = av.w;
        }
        {
            int n = t >> 1;
            int kb = (t & 1) * 8;
            const float* wp = W + (size_t)(n0 + n) * NH + k0 + kb;
            float4 w0 = *(const float4*)(wp);
            float4 w1 = *(const float4*)(wp + 4);
            Bs[kb + 0][n] = w0.x; Bs[kb + 1][n] = w0.y;
            Bs[kb + 2][n] = w0.z; Bs[kb + 3][n] = w0.w;
            Bs[kb + 4][n] = w1.x; Bs[kb + 5][n] = w1.y;
            Bs[kb + 6][n] = w1.z; Bs[kb + 7][n] = w1.w;
        }
        __syncthreads();
#pragma unroll
        for (int k = 0; k < BK; k++) {
            float ar[8], br[8];
#pragma unroll
            for (int i = 0; i < 8; i++) ar[i] = As[k][ty * 8 + i];
#pragma unroll
            for (int j = 0; j < 8; j++) br[j] = Bs[k][tx * 8 + j];
#pragma unroll
            for (int i = 0; i < 8; i++)
#pragma unroll
                for (int j = 0; j < 8; j++) acc[i][j] += ar[i] * br[j];
        }
        __syncthreads();
    }
#pragma unroll
    for (int i = 0; i < 8; i++) {
        int gm = m0 + ty * 8 + i;
        if (gm >= NNODES) break;
#pragma unroll
        for (int j = 0; j < 8; j += 4) {
            int gn = n0 + tx * 8 + j;
            float4 bv = *(const float4*)(bias + gn);
            float4 o;
            o.x = acc[i][j + 0] + bv.x;
            o.y = acc[i][j + 1] + bv.y;
            o.z = acc[i][j + 2] + bv.z;
            o.w = acc[i][j + 3] + bv.w;
            *(float4*)(C + (size_t)gm * NH + gn) = o;
        }
    }
}

// ---------------- CSR SpMM: warp-per-row, register accumulators ----------
template <int NSRC>
__global__ __launch_bounds__(256) void spmm_kernel(const float* __restrict__ s0, int sel0,
                                                   const float* __restrict__ s1, int sel1,
                                                   const float* __restrict__ s2, int sel2,
                                                   float* __restrict__ dst) {
    int w = (blockIdx.x * blockDim.x + threadIdx.x) >> 5;
    int lane = threadIdx.x & 31;
    if (w >= NNODES) return;
    float4 a0 = make_float4(0.f, 0.f, 0.f, 0.f);
    float4 a1 = make_float4(0.f, 0.f, 0.f, 0.f);
    const float* srcs[3] = {s0, s1, s2};
    const int sels[3] = {sel0, sel1, sel2};
#pragma unroll
    for (int s = 0; s < NSRC; s++) {
        int adj = g_adj_idx[sels[s]];
        const int* rp = g_rowptr + adj * (NNODES + 1);
        int beg = __ldg(rp + w), end = __ldg(rp + w + 1);
        const int* ec = g_ecol + (size_t)adj * NEDGE;
        const float* ev = g_eval + (size_t)adj * NEDGE;
        const float* src = srcs[s];
        int c = 0;
        float v = 0.f;
        if (beg < end) { c = __ldg(ec + beg); v = __ldg(ev + beg); }
        for (int e = beg; e < end; e++) {
            int cn = 0;
            float vn = 0.f;
            if (e + 1 < end) { cn = __ldg(ec + e + 1); vn = __ldg(ev + e + 1); }
            const float4* row = (const float4*)(src + (size_t)c * NH);
            float4 p = __ldg(row + lane);
            float4 q = __ldg(row + lane + 32);
            a0.x += v * p.x; a0.y += v * p.y; a0.z += v * p.z; a0.w += v * p.w;
            a1.x += v * q.x; a1.y += v * q.y; a1.z += v * q.z; a1.w += v * q.w;
            c = cn; v = vn;
        }
    }
    float4* drow = (float4*)(dst + (size_t)w * NH);
    drow[lane] = a0;
    drow[lane + 32] = a1;
}

// ---------------- fused step-3 SpMM + LayerNorm + exact GELU -------------
__global__ __launch_bounds__(256) void spmm_ln_gelu_kernel(
    const float* __restrict__ s0, int sel0,
    const float* __restrict__ s1, int sel1,
    const float* __restrict__ s2, int sel2,
    const float* __restrict__ gamma, const float* __restrict__ beta,
    float* __restrict__ out) {
    int w = (blockIdx.x * blockDim.x + threadIdx.x) >> 5;
    int lane = threadIdx.x & 31;
    if (w >= NNODES) return;
    float4 a0 = make_float4(0.f, 0.f, 0.f, 0.f);
    float4 a1 = make_float4(0.f, 0.f, 0.f, 0.f);
    const float* srcs[3] = {s0, s1, s2};
    const int sels[3] = {sel0, sel1, sel2};
#pragma unroll
    for (int s = 0; s < 3; s++) {
        int adj = g_adj_idx[sels[s]];
        const int* rp = g_rowptr + adj * (NNODES + 1);
        int beg = __ldg(rp + w), end = __ldg(rp + w + 1);
        const int* ec = g_ecol + (size_t)adj * NEDGE;
        const float* ev = g_eval + (size_t)adj * NEDGE;
        const float* src = srcs[s];
        int c = 0;
        float v = 0.f;
        if (beg < end) { c = __ldg(ec + beg); v = __ldg(ev + beg); }
        for (int e = beg; e < end; e++) {
            int cn = 0;
            float vn = 0.f;
            if (e + 1 < end) { cn = __ldg(ec + e + 1); vn = __ldg(ev + e + 1); }
            const float4* row = (const float4*)(src + (size_t)c * NH);
            float4 p = __ldg(row + lane);
            float4 q = __ldg(row + lane + 32);
            a0.x += v * p.x; a0.y += v * p.y; a0.z += v * p.z; a0.w += v * p.w;
            a1.x += v * q.x; a1.y += v * q.y; a1.z += v * q.z; a1.w += v * q.w;
            c = cn; v = vn;
        }
    }
    float sum = a0.x + a0.y + a0.z + a0.w + a1.x + a1.y + a1.z + a1.w;
    float sq = a0.x * a0.x + a0.y * a0.y + a0.z * a0.z + a0.w * a0.w +
               a1.x * a1.x + a1.y * a1.y + a1.z * a1.z + a1.w * a1.w;
#pragma unroll
    for (int off = 16; off >= 1; off >>= 1) {
        sum += __shfl_xor_sync(0xFFFFFFFFu, sum, off);
        sq  += __shfl_xor_sync(0xFFFFFFFFu, sq, off);
    }
    float mean = sum * (1.f / NH);
    float var = sq * (1.f / NH) - mean * mean;
    float inv = rsqrtf(var + LN_EPS);

    float4 g0 = __ldg((const float4*)gamma + lane);
    float4 g1 = __ldg((const float4*)gamma + lane + 32);
    float4 b0 = __ldg((const float4*)beta + lane);
    float4 b1 = __ldg((const float4*)beta + lane + 32);

    float xs[8] = {a0.x, a0.y, a0.z, a0.w, a1.x, a1.y, a1.z, a1.w};
    float gs[8] = {g0.x, g0.y, g0.z, g0.w, g1.x, g1.y, g1.z, g1.w};
    float bs[8] = {b0.x, b0.y, b0.z, b0.w, b1.x, b1.y, b1.z, b1.w};
    float r[8];
#pragma unroll
    for (int i = 0; i < 8; i++) {
        float y = (xs[i] - mean) * inv * gs[i] + bs[i];
        r[i] = 0.5f * y * (1.f + erff(y * 0.70710678118654752f));
    }
    float4* orow = (float4*)(out + (size_t)w * NH);
    orow[lane] = make_float4(r[0], r[1], r[2], r[3]);
    orow[lane + 32] = make_float4(r[4], r[5], r[6], r[7]);
}

// ---------------- launch ---------------------------------------------
extern "C" void kernel_launch(void* const* d_in, const int* in_sizes, int n_in,
                              void* d_out, int out_size) {
    const float* x    = (const float*)d_in[0];
    const int* rows   = (const int*)d_in[1];
    const int* cols   = (const int*)d_in[2];
    const float* vals = (const float*)d_in[3];
    const int* seqr   = (const int*)d_in[4];
    const int* resr   = (const int*)d_in[5];
    const float* W    = (const float*)d_in[6];
    const float* b    = (const float*)d_in[7];
    const float* gamma = (const float*)d_in[8];
    const float* beta  = (const float*)d_in[9];
    float* out = (float*)d_out;

    static float *s0 = nullptr, *s1 = nullptr, *s2 = nullptr;
    if (!s0) {
        cudaGetSymbolAddress((void**)&s0, g_state0);
        cudaGetSymbolAddress((void**)&s1, g_state1);
        cudaGetSymbolAddress((void**)&s2, g_state2);
    }

    decode_idx_kernel<<<1, 1>>>(seqr, resr);
    zero_cnt_kernel<<<(NADJ * NNODES + 255) / 256, 256>>>();
    hist_kernel<<<(NADJ * NEDGE + 255) / 256, 256>>>(rows);
    scanA_kernel<<<NADJ * BLK_PER_ADJ, SCAN_B>>>();
    scanB_kernel<<<1, 512>>>();
    scanC_kernel<<<NADJ * BLK_PER_ADJ, SCAN_B>>>();
    scatter_kernel<<<(NADJ * NEDGE + 255) / 256, 256>>>(rows, cols, vals);

    gemm_kernel<<<dim3((NNODES + 127) / 128, NH / 128), 256>>>(x, W, b, s0);

    const int spmm_blocks = (NNODES + 7) / 8;  // warp per row, 8 warps/block
    spmm_kernel<1><<<spmm_blocks, 256>>>(s0, 0, nullptr, 0, nullptr, 0, s1);
    spmm_kernel<2><<<spmm_blocks, 256>>>(s1, 1, s0, 3, nullptr, 0, s2);
    spmm_ln_gelu_kernel<<<spmm_blocks, 256>>>(s2, 2, s0, 4, s1, 5, gamma, beta, out);
}

// round 4
// speedup vs baseline: 1.2801x; 1.1286x over previous
#include <cuda_runtime.h>
#include <math.h>

#define NNODES 50000
#define NADJ   6
#define NEDGE  800000
#define NH     256
#define LN_EPS 1e-5f

#define SCAN_B 1024
#define BLK_PER_ADJ ((NNODES + SCAN_B - 1) / SCAN_B)   // 49

// ---------------- device scratch (no allocations allowed) ----------------
static __device__ float g_state0[(size_t)NNODES * NH];
static __device__ float g_state1[(size_t)NNODES * NH];
static __device__ float g_state2[(size_t)NNODES * NH];
static __device__ int   g_cnt[NADJ * NNODES];
static __device__ int   g_rowptr[NADJ * (NNODES + 1)];
static __device__ int   g_cur[NADJ * NNODES];
static __device__ int   g_blksum[NADJ * BLK_PER_ADJ];
static __device__ int   g_ecol[(size_t)NADJ * NEDGE];
static __device__ float g_eval[(size_t)NADJ * NEDGE];
static __device__ int   g_adj_idx[6];   // [seq0,seq1,seq2,res0,res1,res2]
static __device__ int   g_used[NADJ];

// ---------------- idx decode: int32 vs int64 autodetect -------------------
__global__ void decode_idx_kernel(const int* __restrict__ seq_raw,
                                  const int* __restrict__ res_raw) {
    if (threadIdx.x != 0 || blockIdx.x != 0) return;
    long long a[6];
    int b[6];
    bool v64 = true, v32 = true;
    const long long* s64 = (const long long*)seq_raw;
    const long long* r64 = (const long long*)res_raw;
#pragma unroll
    for (int i = 0; i < 3; i++) {
        long long t = s64[i]; a[i] = t;     if (t < 0 || t >= NADJ) v64 = false;
        long long u = r64[i]; a[3 + i] = u; if (u < 0 || u >= NADJ) v64 = false;
        int p = seq_raw[i]; b[i] = p;       if (p < 0 || p >= NADJ) v32 = false;
        int q = res_raw[i]; b[3 + i] = q;   if (q < 0 || q >= NADJ) v32 = false;
    }
    (void)v32;
#pragma unroll
    for (int i = 0; i < NADJ; i++) g_used[i] = 0;
#pragma unroll
    for (int i = 0; i < 6; i++) {
        int v = v64 ? (int)a[i] : b[i];
        g_adj_idx[i] = v;
        g_used[v] = 1;
    }
}

// ---------------- CSR build --------------------------------------------
__global__ void zero_cnt_kernel() {
    int i = blockIdx.x * blockDim.x + threadIdx.x;
    if (i < NADJ * NNODES) g_cnt[i] = 0;
}

__global__ void hist_kernel(const int* __restrict__ rows) {
    int i = blockIdx.x * blockDim.x + threadIdx.x;
    if (i >= NADJ * NEDGE) return;
    int adj = i / NEDGE;
    if (!g_used[adj]) return;
    int r = rows[i];
    atomicAdd(&g_cnt[adj * NNODES + r], 1);
}

__global__ __launch_bounds__(SCAN_B) void scanA_kernel() {
    __shared__ int s[SCAN_B];
    int bx = blockIdx.x;
    int adj = bx / BLK_PER_ADJ;
    int blk = bx % BLK_PER_ADJ;
    int t = threadIdx.x;
    int i = blk * SCAN_B + t;
    int v = (i < NNODES) ? g_cnt[adj * NNODES + i] : 0;
    s[t] = v;
    __syncthreads();
#pragma unroll
    for (int off = 1; off < SCAN_B; off <<= 1) {
        int u = (t >= off) ? s[t - off] : 0;
        __syncthreads();
        s[t] += u;
        __syncthreads();
    }
    if (i < NNODES) g_cnt[adj * NNODES + i] = s[t] - v;
    if (t == SCAN_B - 1) g_blksum[adj * BLK_PER_ADJ + blk] = s[t];
}

__global__ __launch_bounds__(512) void scanB_kernel() {
    __shared__ int sb[NADJ * BLK_PER_ADJ];
    int t = threadIdx.x;
    for (int i = t; i < NADJ * BLK_PER_ADJ; i += blockDim.x) sb[i] = g_blksum[i];
    __syncthreads();
    if (t < NADJ) {
        int run = 0;
        for (int k = 0; k < BLK_PER_ADJ; k++) {
            int v = sb[t * BLK_PER_ADJ + k];
            sb[t * BLK_PER_ADJ + k] = run;
            run += v;
        }
        g_rowptr[t * (NNODES + 1) + NNODES] = run;
    }
    __syncthreads();
    for (int i = t; i < NADJ * BLK_PER_ADJ; i += blockDim.x) g_blksum[i] = sb[i];
}

__global__ __launch_bounds__(SCAN_B) void scanC_kernel() {
    int bx = blockIdx.x;
    int adj = bx / BLK_PER_ADJ;
    int blk = bx % BLK_PER_ADJ;
    int t = threadIdx.x;
    int i = blk * SCAN_B + t;
    if (i >= NNODES) return;
    int val = g_cnt[adj * NNODES + i] + g_blksum[adj * BLK_PER_ADJ + blk];
    g_rowptr[adj * (NNODES + 1) + i] = val;
    g_cur[adj * NNODES + i] = val;
}

__global__ void scatter_kernel(const int* __restrict__ rows,
                               const int* __restrict__ cols,
                               const float* __restrict__ vals) {
    int i = blockIdx.x * blockDim.x + threadIdx.x;
    if (i >= NADJ * NEDGE) return;
    int adj = i / NEDGE;
    if (!g_used[adj]) return;
    int r = rows[i];
    int pos = atomicAdd(&g_cur[adj * NNODES + r], 1);
    g_ecol[(size_t)adj * NEDGE + pos] = cols[i];
    g_eval[(size_t)adj * NEDGE + pos] = vals[i];
}

// ---------------- TF32 split tensor-core GEMM ----------------------------
// C[m][n] = sum_k A[m][k] * W[n][k] + bias[n]
// A split into tf32 hi + lo; 3 mma passes: hi*hi + hi*lo + lo*hi.
#define GBM 128
#define GBN 128
#define GBK 16
#define SPAD 20   // row stride in words for [row][k] smem layout (conflict-free)

__device__ __forceinline__ float f2tf32(float x) {
    float r;
    asm("cvt.rna.tf32.f32 %0, %1;" : "=f"(r) : "f"(x));
    return r;
}

__device__ __forceinline__ void mma_tf32(float* d, const float* a, float b0, float b1) {
    asm volatile(
        "mma.sync.aligned.m16n8k8.row.col.f32.tf32.tf32.f32 "
        "{%0,%1,%2,%3}, {%4,%5,%6,%7}, {%8,%9}, {%0,%1,%2,%3};"
        : "+f"(d[0]), "+f"(d[1]), "+f"(d[2]), "+f"(d[3])
        : "r"(__float_as_uint(a[0])), "r"(__float_as_uint(a[1])),
          "r"(__float_as_uint(a[2])), "r"(__float_as_uint(a[3])),
          "r"(__float_as_uint(b0)), "r"(__float_as_uint(b1)));
}

__global__ __launch_bounds__(256) void gemm_tf32_kernel(
    const float* __restrict__ A, const float* __restrict__ W,
    const float* __restrict__ bias, float* __restrict__ C) {
    __shared__ float As_hi[GBM][SPAD];
    __shared__ float As_lo[GBM][SPAD];
    __shared__ float Bs_hi[GBN][SPAD];
    __shared__ float Bs_lo[GBN][SPAD];

    int t = threadIdx.x;
    int m0 = blockIdx.x * GBM;
    int n0 = blockIdx.y * GBN;
    int ws = t >> 5, lane = t & 31;
    int wm = ws & 3, wn = ws >> 2;      // 4 warps along M, 2 along N
    int g = lane >> 2, t4 = lane & 3;

    float acc[2][8][4];
#pragma unroll
    for (int i = 0; i < 2; i++)
#pragma unroll
        for (int j = 0; j < 8; j++)
#pragma unroll
            for (int q = 0; q < 4; q++) acc[i][j][q] = 0.f;

    for (int k0 = 0; k0 < NH; k0 += GBK) {
        // load A tile 128x16 (2 float4 per thread), split hi/lo
#pragma unroll
        for (int L = 0; L < 2; L++) {
            int f = t + L * 256;
            int m = f >> 2, c4 = f & 3;
            int gm = m0 + m;
            float4 v = make_float4(0.f, 0.f, 0.f, 0.f);
            if (gm < NNODES)
                v = *(const float4*)(A + (size_t)gm * NH + k0 + c4 * 4);
            float4 h, l;
            h.x = f2tf32(v.x); l.x = f2tf32(v.x - h.x);
            h.y = f2tf32(v.y); l.y = f2tf32(v.y - h.y);
            h.z = f2tf32(v.z); l.z = f2tf32(v.z - h.z);
            h.w = f2tf32(v.w); l.w = f2tf32(v.w - h.w);
            *(float4*)&As_hi[m][c4 * 4] = h;
            *(float4*)&As_lo[m][c4 * 4] = l;
        }
        // load B tile: Bs[n][k] = W[n0+n][k0+k]
#pragma unroll
        for (int L = 0; L < 2; L++) {
            int f = t + L * 256;
            int n = f >> 2, c4 = f & 3;
            float4 v = *(const float4*)(W + (size_t)(n0 + n) * NH + k0 + c4 * 4);
            float4 h, l;
            h.x = f2tf32(v.x); l.x = f2tf32(v.x - h.x);
            h.y = f2tf32(v.y); l.y = f2tf32(v.y - h.y);
            h.z = f2tf32(v.z); l.z = f2tf32(v.z - h.z);
            h.w = f2tf32(v.w); l.w = f2tf32(v.w - h.w);
            *(float4*)&Bs_hi[n][c4 * 4] = h;
            *(float4*)&Bs_lo[n][c4 * 4] = l;
        }
        __syncthreads();

#pragma unroll
        for (int k8 = 0; k8 < GBK / 8; k8++) {
            int kb = k8 * 8;
            float ah[2][4], al[2][4];
#pragma unroll
            for (int i = 0; i < 2; i++) {
                int mr = wm * 32 + i * 16;
                ah[i][0] = As_hi[mr + g][kb + t4];
                ah[i][1] = As_hi[mr + g + 8][kb + t4];
                ah[i][2] = As_hi[mr + g][kb + t4 + 4];
                ah[i][3] = As_hi[mr + g + 8][kb + t4 + 4];
                al[i][0] = As_lo[mr + g][kb + t4];
                al[i][1] = As_lo[mr + g + 8][kb + t4];
                al[i][2] = As_lo[mr + g][kb + t4 + 4];
                al[i][3] = As_lo[mr + g + 8][kb + t4 + 4];
            }
#pragma unroll
            for (int j = 0; j < 8; j++) {
                int nb = wn * 64 + j * 8;
                float b0h = Bs_hi[nb + g][kb + t4];
                float b1h = Bs_hi[nb + g][kb + t4 + 4];
                float b0l = Bs_lo[nb + g][kb + t4];
                float b1l = Bs_lo[nb + g][kb + t4 + 4];
#pragma unroll
                for (int i = 0; i < 2; i++) {
                    mma_tf32(acc[i][j], ah[i], b0h, b1h);
                    mma_tf32(acc[i][j], ah[i], b0l, b1l);
                    mma_tf32(acc[i][j], al[i], b0h, b1h);
                }
            }
        }
        __syncthreads();
    }

    // epilogue: + bias, store
#pragma unroll
    for (int j = 0; j < 8; j++) {
        int c = n0 + wn * 64 + j * 8 + 2 * t4;
        float bx = __ldg(bias + c);
        float by = __ldg(bias + c + 1);
#pragma unroll
        for (int i = 0; i < 2; i++) {
            int r0 = m0 + wm * 32 + i * 16 + g;
            if (r0 < NNODES) {
                float2 o0 = make_float2(acc[i][j][0] + bx, acc[i][j][1] + by);
                *(float2*)(C + (size_t)r0 * NH + c) = o0;
            }
            int r1 = r0 + 8;
            if (r1 < NNODES) {
                float2 o1 = make_float2(acc[i][j][2] + bx, acc[i][j][3] + by);
                *(float2*)(C + (size_t)r1 * NH + c) = o1;
            }
        }
    }
}

// ---------------- CSR SpMM: warp-per-row, register accumulators ----------
template <int NSRC>
__global__ __launch_bounds__(256) void spmm_kernel(const float* __restrict__ s0, int sel0,
                                                   const float* __restrict__ s1, int sel1,
                                                   const float* __restrict__ s2, int sel2,
                                                   float* __restrict__ dst) {
    int w = (blockIdx.x * blockDim.x + threadIdx.x) >> 5;
    int lane = threadIdx.x & 31;
    if (w >= NNODES) return;
    float4 a0 = make_float4(0.f, 0.f, 0.f, 0.f);
    float4 a1 = make_float4(0.f, 0.f, 0.f, 0.f);
    const float* srcs[3] = {s0, s1, s2};
    const int sels[3] = {sel0, sel1, sel2};
#pragma unroll
    for (int s = 0; s < NSRC; s++) {
        int adj = g_adj_idx[sels[s]];
        const int* rp = g_rowptr + adj * (NNODES + 1);
        int beg = __ldg(rp + w), end = __ldg(rp + w + 1);
        const int* ec = g_ecol + (size_t)adj * NEDGE;
        const float* ev = g_eval + (size_t)adj * NEDGE;
        const float* src = srcs[s];
        int c = 0;
        float v = 0.f;
        if (beg < end) { c = __ldg(ec + beg); v = __ldg(ev + beg); }
        for (int e = beg; e < end; e++) {
            int cn = 0;
            float vn = 0.f;
            if (e + 1 < end) { cn = __ldg(ec + e + 1); vn = __ldg(ev + e + 1); }
            const float4* row = (const float4*)(src + (size_t)c * NH);
            float4 p = __ldg(row + lane);
            float4 q = __ldg(row + lane + 32);
            a0.x += v * p.x; a0.y += v * p.y; a0.z += v * p.z; a0.w += v * p.w;
            a1.x += v * q.x; a1.y += v * q.y; a1.z += v * q.z; a1.w += v * q.w;
            c = cn; v = vn;
        }
    }
    float4* drow = (float4*)(dst + (size_t)w * NH);
    drow[lane] = a0;
    drow[lane + 32] = a1;
}

// ---------------- fused step-3 SpMM + LayerNorm + exact GELU -------------
__global__ __launch_bounds__(256) void spmm_ln_gelu_kernel(
    const float* __restrict__ s0, int sel0,
    const float* __restrict__ s1, int sel1,
    const float* __restrict__ s2, int sel2,
    const float* __restrict__ gamma, const float* __restrict__ beta,
    float* __restrict__ out) {
    int w = (blockIdx.x * blockDim.x + threadIdx.x) >> 5;
    int lane = threadIdx.x & 31;
    if (w >= NNODES) return;
    float4 a0 = make_float4(0.f, 0.f, 0.f, 0.f);
    float4 a1 = make_float4(0.f, 0.f, 0.f, 0.f);
    const float* srcs[3] = {s0, s1, s2};
    const int sels[3] = {sel0, sel1, sel2};
#pragma unroll
    for (int s = 0; s < 3; s++) {
        int adj = g_adj_idx[sels[s]];
        const int* rp = g_rowptr + adj * (NNODES + 1);
        int beg = __ldg(rp + w), end = __ldg(rp + w + 1);
        const int* ec = g_ecol + (size_t)adj * NEDGE;
        const float* ev = g_eval + (size_t)adj * NEDGE;
        const float* src = srcs[s];
        int c = 0;
        float v = 0.f;
        if (beg < end) { c = __ldg(ec + beg); v = __ldg(ev + beg); }
        for (int e = beg; e < end; e++) {
            int cn = 0;
            float vn = 0.f;
            if (e + 1 < end) { cn = __ldg(ec + e + 1); vn = __ldg(ev + e + 1); }
            const float4* row = (const float4*)(src + (size_t)c * NH);
            float4 p = __ldg(row + lane);
            float4 q = __ldg(row + lane + 32);
            a0.x += v * p.x; a0.y += v * p.y; a0.z += v * p.z; a0.w += v * p.w;
            a1.x += v * q.x; a1.y += v * q.y; a1.z += v * q.z; a1.w += v * q.w;
            c = cn; v = vn;
        }
    }
    float sum = a0.x + a0.y + a0.z + a0.w + a1.x + a1.y + a1.z + a1.w;
    float sq = a0.x * a0.x + a0.y * a0.y + a0.z * a0.z + a0.w * a0.w +
               a1.x * a1.x + a1.y * a1.y + a1.z * a1.z + a1.w * a1.w;
#pragma unroll
    for (int off = 16; off >= 1; off >>= 1) {
        sum += __shfl_xor_sync(0xFFFFFFFFu, sum, off);
        sq  += __shfl_xor_sync(0xFFFFFFFFu, sq, off);
    }
    float mean = sum * (1.f / NH);
    float var = sq * (1.f / NH) - mean * mean;
    float inv = rsqrtf(var + LN_EPS);

    float4 g0 = __ldg((const float4*)gamma + lane);
    float4 g1 = __ldg((const float4*)gamma + lane + 32);
    float4 b0 = __ldg((const float4*)beta + lane);
    float4 b1 = __ldg((const float4*)beta + lane + 32);

    float xs[8] = {a0.x, a0.y, a0.z, a0.w, a1.x, a1.y, a1.z, a1.w};
    float gs[8] = {g0.x, g0.y, g0.z, g0.w, g1.x, g1.y, g1.z, g1.w};
    float bs[8] = {b0.x, b0.y, b0.z, b0.w, b1.x, b1.y, b1.z, b1.w};
    float r[8];
#pragma unroll
    for (int i = 0; i < 8; i++) {
        float y = (xs[i] - mean) * inv * gs[i] + bs[i];
        r[i] = 0.5f * y * (1.f + erff(y * 0.70710678118654752f));
    }
    float4* orow = (float4*)(out + (size_t)w * NH);
    orow[lane] = make_float4(r[0], r[1], r[2], r[3]);
    orow[lane + 32] = make_float4(r[4], r[5], r[6], r[7]);
}

// ---------------- launch ---------------------------------------------
extern "C" void kernel_launch(void* const* d_in, const int* in_sizes, int n_in,
                              void* d_out, int out_size) {
    const float* x    = (const float*)d_in[0];
    const int* rows   = (const int*)d_in[1];
    const int* cols   = (const int*)d_in[2];
    const float* vals = (const float*)d_in[3];
    const int* seqr   = (const int*)d_in[4];
    const int* resr   = (const int*)d_in[5];
    const float* W    = (const float*)d_in[6];
    const float* b    = (const float*)d_in[7];
    const float* gamma = (const float*)d_in[8];
    const float* beta  = (const float*)d_in[9];
    float* out = (float*)d_out;

    static float *s0p = nullptr, *s1p = nullptr, *s2p = nullptr;
    static cudaStream_t st2;
    static cudaEvent_t evFork, evJoin;
    if (!s0p) {
        cudaGetSymbolAddress((void**)&s0p, g_state0);
        cudaGetSymbolAddress((void**)&s1p, g_state1);
        cudaGetSymbolAddress((void**)&s2p, g_state2);
        cudaStreamCreateWithFlags(&st2, cudaStreamNonBlocking);
        cudaEventCreateWithFlags(&evFork, cudaEventDisableTiming);
        cudaEventCreateWithFlags(&evJoin, cudaEventDisableTiming);
    }

    // fork: GEMM on st2 runs concurrently with the CSR build chain
    cudaEventRecord(evFork, 0);
    cudaStreamWaitEvent(st2, evFork, 0);
    gemm_tf32_kernel<<<dim3((NNODES + GBM - 1) / GBM, NH / GBN), 256, 0, st2>>>(x, W, b, s0p);
    cudaEventRecord(evJoin, st2);

    // CSR build on the main (captured) stream
    decode_idx_kernel<<<1, 1>>>(seqr, resr);
    zero_cnt_kernel<<<(NADJ * NNODES + 255) / 256, 256>>>();
    hist_kernel<<<(NADJ * NEDGE + 255) / 256, 256>>>(rows);
    scanA_kernel<<<NADJ * BLK_PER_ADJ, SCAN_B>>>();
    scanB_kernel<<<1, 512>>>();
    scanC_kernel<<<NADJ * BLK_PER_ADJ, SCAN_B>>>();
    scatter_kernel<<<(NADJ * NEDGE + 255) / 256, 256>>>(rows, cols, vals);

    // join: SpMM chain needs both GEMM output and CSR
    cudaStreamWaitEvent(0, evJoin, 0);

    const int spmm_blocks = (NNODES + 7) / 8;  // warp per row, 8 warps/block
    spmm_kernel<1><<<spmm_blocks, 256>>>(s0p, 0, nullptr, 0, nullptr, 0, s1p);
    spmm_kernel<2><<<spmm_blocks, 256>>>(s1p, 1, s0p, 3, nullptr, 0, s2p);
    spmm_ln_gelu_kernel<<<spmm_blocks, 256>>>(s2p, 2, s0p, 4, s1p, 5, gamma, beta, out);
}

// round 6
// speedup vs baseline: 1.9263x; 1.5047x over previous
#include <cuda_runtime.h>
#include <cuda_fp16.h>
#include <math.h>

#define NNODES 50000
#define NADJ   6
#define NEDGE  800000
#define NH     256
#define LN_EPS 1e-5f

#define SCAN_B 1024
#define BLK_PER_ADJ ((NNODES + SCAN_B - 1) / SCAN_B)   // 49

// ---------------- device scratch (no allocations allowed) ----------------
static __device__ __align__(16) __half g_state0[(size_t)NNODES * NH];
static __device__ __align__(16) __half g_state1[(size_t)NNODES * NH];
static __device__ __align__(16) __half g_state2[(size_t)NNODES * NH];
static __device__ int   g_cnt[NADJ * NNODES];
static __device__ int   g_rowptr[NADJ * (NNODES + 1)];
static __device__ int   g_cur[NADJ * NNODES];
static __device__ int   g_blksum[NADJ * BLK_PER_ADJ];
static __device__ __align__(16) int2 g_edge[(size_t)NADJ * NEDGE];  // {col, val bits}
static __device__ int   g_adj_idx[6];   // [seq0,seq1,seq2,res0,res1,res2]
static __device__ int   g_used[NADJ];

// ---------------- idx decode: int32 vs int64 autodetect -------------------
__global__ void decode_idx_kernel(const int* __restrict__ seq_raw,
                                  const int* __restrict__ res_raw) {
    if (threadIdx.x != 0 || blockIdx.x != 0) return;
    long long a[6];
    int b[6];
    bool v64 = true, v32 = true;
    const long long* s64 = (const long long*)seq_raw;
    const long long* r64 = (const long long*)res_raw;
#pragma unroll
    for (int i = 0; i < 3; i++) {
        long long t = s64[i]; a[i] = t;     if (t < 0 || t >= NADJ) v64 = false;
        long long u = r64[i]; a[3 + i] = u; if (u < 0 || u >= NADJ) v64 = false;
        int p = seq_raw[i]; b[i] = p;       if (p < 0 || p >= NADJ) v32 = false;
        int q = res_raw[i]; b[3 + i] = q;   if (q < 0 || q >= NADJ) v32 = false;
    }
    (void)v32;
#pragma unroll
    for (int i = 0; i < NADJ; i++) g_used[i] = 0;
#pragma unroll
    for (int i = 0; i < 6; i++) {
        int v = v64 ? (int)a[i] : b[i];
        g_adj_idx[i] = v;
        g_used[v] = 1;
    }
}

// ---------------- CSR build --------------------------------------------
__global__ void zero_cnt_kernel() {
    int i = blockIdx.x * blockDim.x + threadIdx.x;
    if (i < NADJ * NNODES) g_cnt[i] = 0;
}

__global__ void hist_kernel(const int* __restrict__ rows) {
    int i = blockIdx.x * blockDim.x + threadIdx.x;
    if (i >= NADJ * NEDGE) return;
    int adj = i / NEDGE;
    if (!g_used[adj]) return;
    int r = rows[i];
    atomicAdd(&g_cnt[adj * NNODES + r], 1);
}

__global__ __launch_bounds__(SCAN_B) void scanA_kernel() {
    __shared__ int s[SCAN_B];
    int bx = blockIdx.x;
    int adj = bx / BLK_PER_ADJ;
    int blk = bx % BLK_PER_ADJ;
    int t = threadIdx.x;
    int i = blk * SCAN_B + t;
    int v = (i < NNODES) ? g_cnt[adj * NNODES + i] : 0;
    s[t] = v;
    __syncthreads();
#pragma unroll
    for (int off = 1; off < SCAN_B; off <<= 1) {
        int u = (t >= off) ? s[t - off] : 0;
        __syncthreads();
        s[t] += u;
        __syncthreads();
    }
    if (i < NNODES) g_cnt[adj * NNODES + i] = s[t] - v;
    if (t == SCAN_B - 1) g_blksum[adj * BLK_PER_ADJ + blk] = s[t];
}

__global__ __launch_bounds__(512) void scanB_kernel() {
    __shared__ int sb[NADJ * BLK_PER_ADJ];
    int t = threadIdx.x;
    for (int i = t; i < NADJ * BLK_PER_ADJ; i += blockDim.x) sb[i] = g_blksum[i];
    __syncthreads();
    if (t < NADJ) {
        int run = 0;
        for (int k = 0; k < BLK_PER_ADJ; k++) {
            int v = sb[t * BLK_PER_ADJ + k];
            sb[t * BLK_PER_ADJ + k] = run;
            run += v;
        }
        g_rowptr[t * (NNODES + 1) + NNODES] = run;
    }
    __syncthreads();
    for (int i = t; i < NADJ * BLK_PER_ADJ; i += blockDim.x) g_blksum[i] = sb[i];
}

__global__ __launch_bounds__(SCAN_B) void scanC_kernel() {
    int bx = blockIdx.x;
    int adj = bx / BLK_PER_ADJ;
    int blk = bx % BLK_PER_ADJ;
    int t = threadIdx.x;
    int i = blk * SCAN_B + t;
    if (i >= NNODES) return;
    int val = g_cnt[adj * NNODES + i] + g_blksum[adj * BLK_PER_ADJ + blk];
    g_rowptr[adj * (NNODES + 1) + i] = val;
    g_cur[adj * NNODES + i] = val;
}

__global__ void scatter_kernel(const int* __restrict__ rows,
                               const int* __restrict__ cols,
                               const float* __restrict__ vals) {
    int i = blockIdx.x * blockDim.x + threadIdx.x;
    if (i >= NADJ * NEDGE) return;
    int adj = i / NEDGE;
    if (!g_used[adj]) return;
    int r = rows[i];
    int pos = atomicAdd(&g_cur[adj * NNODES + r], 1);
    g_edge[(size_t)adj * NEDGE + pos] = make_int2(cols[i], __float_as_int(vals[i]));
}

// ---------------- TF32 split tensor-core GEMM, fp16 output ----------------
#define GBM 128
#define GBN 128
#define GBK 16
#define SPAD 20

__device__ __forceinline__ float f2tf32(float x) {
    float r;
    asm("cvt.rna.tf32.f32 %0, %1;" : "=f"(r) : "f"(x));
    return r;
}

__device__ __forceinline__ void mma_tf32(float* d, const float* a, float b0, float b1) {
    asm volatile(
        "mma.sync.aligned.m16n8k8.row.col.f32.tf32.tf32.f32 "
        "{%0,%1,%2,%3}, {%4,%5,%6,%7}, {%8,%9}, {%0,%1,%2,%3};"
        : "+f"(d[0]), "+f"(d[1]), "+f"(d[2]), "+f"(d[3])
        : "r"(__float_as_uint(a[0])), "r"(__float_as_uint(a[1])),
          "r"(__float_as_uint(a[2])), "r"(__float_as_uint(a[3])),
          "r"(__float_as_uint(b0)), "r"(__float_as_uint(b1)));
}

__global__ __launch_bounds__(256) void gemm_tf32_kernel(
    const float* __restrict__ A, const float* __restrict__ W,
    const float* __restrict__ bias, __half* __restrict__ C) {
    __shared__ float As_hi[GBM][SPAD];
    __shared__ float As_lo[GBM][SPAD];
    __shared__ float Bs_hi[GBN][SPAD];
    __shared__ float Bs_lo[GBN][SPAD];

    int t = threadIdx.x;
    int m0 = blockIdx.x * GBM;
    int n0 = blockIdx.y * GBN;
    int ws = t >> 5, lane = t & 31;
    int wm = ws & 3, wn = ws >> 2;
    int g = lane >> 2, t4 = lane & 3;

    float acc[2][8][4];
#pragma unroll
    for (int i = 0; i < 2; i++)
#pragma unroll
        for (int j = 0; j < 8; j++)
#pragma unroll
            for (int q = 0; q < 4; q++) acc[i][j][q] = 0.f;

    for (int k0 = 0; k0 < NH; k0 += GBK) {
#pragma unroll
        for (int L = 0; L < 2; L++) {
            int f = t + L * 256;
            int m = f >> 2, c4 = f & 3;
            int gm = m0 + m;
            float4 v = make_float4(0.f, 0.f, 0.f, 0.f);
            if (gm < NNODES)
                v = *(const float4*)(A + (size_t)gm * NH + k0 + c4 * 4);
            float4 h, l;
            h.x = f2tf32(v.x); l.x = f2tf32(v.x - h.x);
            h.y = f2tf32(v.y); l.y = f2tf32(v.y - h.y);
            h.z = f2tf32(v.z); l.z = f2tf32(v.z - h.z);
            h.w = f2tf32(v.w); l.w = f2tf32(v.w - h.w);
            *(float4*)&As_hi[m][c4 * 4] = h;
            *(float4*)&As_lo[m][c4 * 4] = l;
        }
#pragma unroll
        for (int L = 0; L < 2; L++) {
            int f = t + L * 256;
            int n = f >> 2, c4 = f & 3;
            float4 v = *(const float4*)(W + (size_t)(n0 + n) * NH + k0 + c4 * 4);
            float4 h, l;
            h.x = f2tf32(v.x); l.x = f2tf32(v.x - h.x);
            h.y = f2tf32(v.y); l.y = f2tf32(v.y - h.y);
            h.z = f2tf32(v.z); l.z = f2tf32(v.z - h.z);
            h.w = f2tf32(v.w); l.w = f2tf32(v.w - h.w);
            *(float4*)&Bs_hi[n][c4 * 4] = h;
            *(float4*)&Bs_lo[n][c4 * 4] = l;
        }
        __syncthreads();

#pragma unroll
        for (int k8 = 0; k8 < GBK / 8; k8++) {
            int kb = k8 * 8;
            float ah[2][4], al[2][4];
#pragma unroll
            for (int i = 0; i < 2; i++) {
                int mr = wm * 32 + i * 16;
                ah[i][0] = As_hi[mr + g][kb + t4];
                ah[i][1] = As_hi[mr + g + 8][kb + t4];
                ah[i][2] = As_hi[mr + g][kb + t4 + 4];
                ah[i][3] = As_hi[mr + g + 8][kb + t4 + 4];
                al[i][0] = As_lo[mr + g][kb + t4];
                al[i][1] = As_lo[mr + g + 8][kb + t4];
                al[i][2] = As_lo[mr + g][kb + t4 + 4];
                al[i][3] = As_lo[mr + g + 8][kb + t4 + 4];
            }
#pragma unroll
            for (int j = 0; j < 8; j++) {
                int nb = wn * 64 + j * 8;
                float b0h = Bs_hi[nb + g][kb + t4];
                float b1h = Bs_hi[nb + g][kb + t4 + 4];
                float b0l = Bs_lo[nb + g][kb + t4];
                float b1l = Bs_lo[nb + g][kb + t4 + 4];
#pragma unroll
                for (int i = 0; i < 2; i++) {
                    mma_tf32(acc[i][j], ah[i], b0h, b1h);
                    mma_tf32(acc[i][j], ah[i], b0l, b1l);
                    mma_tf32(acc[i][j], al[i], b0h, b1h);
                }
            }
        }
        __syncthreads();
    }

    // epilogue: + bias, convert to fp16, store half2
#pragma unroll
    for (int j = 0; j < 8; j++) {
        int c = n0 + wn * 64 + j * 8 + 2 * t4;
        float bx = __ldg(bias + c);
        float by = __ldg(bias + c + 1);
#pragma unroll
        for (int i = 0; i < 2; i++) {
            int r0 = m0 + wm * 32 + i * 16 + g;
            if (r0 < NNODES) {
                *(half2*)(C + (size_t)r0 * NH + c) =
                    __floats2half2_rn(acc[i][j][0] + bx, acc[i][j][1] + by);
            }
            int r1 = r0 + 8;
            if (r1 < NNODES) {
                *(half2*)(C + (size_t)r1 * NH + c) =
                    __floats2half2_rn(acc[i][j][2] + bx, acc[i][j][3] + by);
            }
        }
    }
}

// ---------------- CSR SpMM: warp-per-row, fp16 gather, fp32 accum ---------
// Each lane owns 8 consecutive cols (lane*8 .. lane*8+7) = one uint4 of halves.
__device__ __forceinline__ void gather_accum(float* acc, const __half* __restrict__ src,
                                             int c, float v, int lane) {
    const uint4* row = (const uint4*)(src + (size_t)c * NH);
    uint4 pv = __ldg(row + lane);
    const __half2* h = (const __half2*)&pv;
    float2 f0 = __half22float2(h[0]);
    float2 f1 = __half22float2(h[1]);
    float2 f2 = __half22float2(h[2]);
    float2 f3 = __half22float2(h[3]);
    acc[0] += v * f0.x; acc[1] += v * f0.y;
    acc[2] += v * f1.x; acc[3] += v * f1.y;
    acc[4] += v * f2.x; acc[5] += v * f2.y;
    acc[6] += v * f3.x; acc[7] += v * f3.y;
}

template <int NSRC>
__device__ __forceinline__ void spmm_accum(float* acc, int w, int lane,
                                           const __half* __restrict__ s0, int sel0,
                                           const __half* __restrict__ s1, int sel1,
                                           const __half* __restrict__ s2, int sel2) {
    const __half* srcs[3] = {s0, s1, s2};
    const int sels[3] = {sel0, sel1, sel2};
#pragma unroll
    for (int s = 0; s < NSRC; s++) {
        int adj = g_adj_idx[sels[s]];
        const int* rp = g_rowptr + adj * (NNODES + 1);
        int beg = __ldg(rp + w), end = __ldg(rp + w + 1);
        const int2* ed = g_edge + (size_t)adj * NEDGE;
        const __half* src = srcs[s];
        int2 e0 = make_int2(0, 0);
        if (beg < end) e0 = __ldg(ed + beg);
        for (int e = beg; e < end; e++) {
            int2 en = make_int2(0, 0);
            if (e + 1 < end) en = __ldg(ed + e + 1);
            gather_accum(acc, src, e0.x, __int_as_float(e0.y), lane);
            e0 = en;
        }
    }
}

template <int NSRC>
__global__ __launch_bounds__(256) void spmm_kernel(const __half* __restrict__ s0, int sel0,
                                                   const __half* __restrict__ s1, int sel1,
                                                   const __half* __restrict__ s2, int sel2,
                                                   __half* __restrict__ dst) {
    int w = (blockIdx.x * blockDim.x + threadIdx.x) >> 5;
    int lane = threadIdx.x & 31;
    if (w >= NNODES) return;
    float acc[8];
#pragma unroll
    for (int i = 0; i < 8; i++) acc[i] = 0.f;
    spmm_accum<NSRC>(acc, w, lane, s0, sel0, s1, sel1, s2, sel2);
    // pack 8 fp32 -> 4 half2 -> uint4, one 16B store per lane
    uint4 pk;
    half2* ph = (half2*)&pk;
    ph[0] = __floats2half2_rn(acc[0], acc[1]);
    ph[1] = __floats2half2_rn(acc[2], acc[3]);
    ph[2] = __floats2half2_rn(acc[4], acc[5]);
    ph[3] = __floats2half2_rn(acc[6], acc[7]);
    ((uint4*)(dst + (size_t)w * NH))[lane] = pk;
}

// ---------------- fused step-3 SpMM + LayerNorm + exact GELU -------------
__global__ __launch_bounds__(256) void spmm_ln_gelu_kernel(
    const __half* __restrict__ s0, int sel0,
    const __half* __restrict__ s1, int sel1,
    const __half* __restrict__ s2, int sel2,
    const float* __restrict__ gamma, const float* __restrict__ beta,
    float* __restrict__ out) {
    int w = (blockIdx.x * blockDim.x + threadIdx.x) >> 5;
    int lane = threadIdx.x & 31;
    if (w >= NNODES) return;
    float acc[8];
#pragma unroll
    for (int i = 0; i < 8; i++) acc[i] = 0.f;
    spmm_accum<3>(acc, w, lane, s0, sel0, s1, sel1, s2, sel2);

    float sum = 0.f, sq = 0.f;
#pragma unroll
    for (int i = 0; i < 8; i++) { sum += acc[i]; sq += acc[i] * acc[i]; }
#pragma unroll
    for (int off = 16; off >= 1; off >>= 1) {
        sum += __shfl_xor_sync(0xFFFFFFFFu, sum, off);
        sq  += __shfl_xor_sync(0xFFFFFFFFu, sq, off);
    }
    float mean = sum * (1.f / NH);
    float var = sq * (1.f / NH) - mean * mean;
    float inv = rsqrtf(var + LN_EPS);

    // lane owns cols lane*8 .. lane*8+7
    const float4* g4 = (const float4*)gamma;
    const float4* b4 = (const float4*)beta;
    float4 ga = __ldg(g4 + lane * 2), gb = __ldg(g4 + lane * 2 + 1);
    float4 ba = __ldg(b4 + lane * 2), bb = __ldg(b4 + lane * 2 + 1);
    float gs[8] = {ga.x, ga.y, ga.z, ga.w, gb.x, gb.y, gb.z, gb.w};
    float bs[8] = {ba.x, ba.y, ba.z, ba.w, bb.x, bb.y, bb.z, bb.w};
    float r[8];
#pragma unroll
    for (int i = 0; i < 8; i++) {
        float y = (acc[i] - mean) * inv * gs[i] + bs[i];
        r[i] = 0.5f * y * (1.f + erff(y * 0.70710678118654752f));
    }
    float4* o4 = (float4*)(out + (size_t)w * NH);
    o4[lane * 2] = make_float4(r[0], r[1], r[2], r[3]);
    o4[lane * 2 + 1] = make_float4(r[4], r[5], r[6], r[7]);
}

// ---------------- launch ---------------------------------------------
extern "C" void kernel_launch(void* const* d_in, const int* in_sizes, int n_in,
                              void* d_out, int out_size) {
    const float* x    = (const float*)d_in[0];
    const int* rows   = (const int*)d_in[1];
    const int* cols   = (const int*)d_in[2];
    const float* vals = (const float*)d_in[3];
    const int* seqr   = (const int*)d_in[4];
    const int* resr   = (const int*)d_in[5];
    const float* W    = (const float*)d_in[6];
    const float* b    = (const float*)d_in[7];
    const float* gamma = (const float*)d_in[8];
    const float* beta  = (const float*)d_in[9];
    float* out = (float*)d_out;

    static __half *s0p = nullptr, *s1p = nullptr, *s2p = nullptr;
    static cudaStream_t st2;
    static cudaEvent_t evFork, evJoin;
    if (!s0p) {
        cudaGetSymbolAddress((void**)&s0p, g_state0);
        cudaGetSymbolAddress((void**)&s1p, g_state1);
        cudaGetSymbolAddress((void**)&s2p, g_state2);
        cudaStreamCreateWithFlags(&st2, cudaStreamNonBlocking);
        cudaEventCreateWithFlags(&evFork, cudaEventDisableTiming);
        cudaEventCreateWithFlags(&evJoin, cudaEventDisableTiming);
    }

    // fork: GEMM on st2 runs concurrently with the CSR build chain
    cudaEventRecord(evFork, 0);
    cudaStreamWaitEvent(st2, evFork, 0);
    gemm_tf32_kernel<<<dim3((NNODES + GBM - 1) / GBM, NH / GBN), 256, 0, st2>>>(x, W, b, s0p);
    cudaEventRecord(evJoin, st2);

    // CSR build on the main (captured) stream
    decode_idx_kernel<<<1, 1>>>(seqr, resr);
    zero_cnt_kernel<<<(NADJ * NNODES + 255) / 256, 256>>>();
    hist_kernel<<<(NADJ * NEDGE + 255) / 256, 256>>>(rows);
    scanA_kernel<<<NADJ * BLK_PER_ADJ, SCAN_B>>>();
    scanB_kernel<<<1, 512>>>();
    scanC_kernel<<<NADJ * BLK_PER_ADJ, SCAN_B>>>();
    scatter_kernel<<<(NADJ * NEDGE + 255) / 256, 256>>>(rows, cols, vals);

    // join: SpMM chain needs both GEMM output and CSR
    cudaStreamWaitEvent(0, evJoin, 0);

    const int spmm_blocks = (NNODES + 7) / 8;  // warp per row, 8 warps/block
    spmm_kernel<1><<<spmm_blocks, 256>>>(s0p, 0, nullptr, 0, nullptr, 0, s1p);
    spmm_kernel<2><<<spmm_blocks, 256>>>(s1p, 1, s0p, 3, nullptr, 0, s2p);
    spmm_ln_gelu_kernel<<<spmm_blocks, 256>>>(s2p, 2, s0p, 4, s1p, 5, gamma, beta, out);
}

// round 7
// speedup vs baseline: 1.9306x; 1.0022x over previous
#include <cuda_runtime.h>
#include <cuda_fp16.h>
#include <math.h>

#define NNODES 50000
#define NADJ   6
#define NEDGE  800000
#define NH     256
#define LN_EPS 1e-5f

#define SCAN_B 1024
#define BLK_PER_ADJ ((NNODES + SCAN_B - 1) / SCAN_B)   // 49

// ---------------- device scratch (no allocations allowed) ----------------
static __device__ __align__(16) __half g_state0[(size_t)NNODES * NH];
static __device__ __align__(16) __half g_state1[(size_t)NNODES * NH];
static __device__ __align__(16) __half g_state2[(size_t)NNODES * NH];
static __device__ int   g_cnt[NADJ * NNODES];
static __device__ int   g_rowptr[NADJ * (NNODES + 1)];
static __device__ int   g_cur[NADJ * NNODES];
static __device__ int   g_blksum[NADJ * BLK_PER_ADJ];
static __device__ __align__(16) int2 g_edge[(size_t)NADJ * NEDGE];  // {col, val bits}
static __device__ int   g_adj_idx[6];   // [seq0,seq1,seq2,res0,res1,res2]
static __device__ int   g_used[NADJ];

// ---------------- idx decode: int32 vs int64 autodetect -------------------
__global__ void decode_idx_kernel(const int* __restrict__ seq_raw,
                                  const int* __restrict__ res_raw) {
    if (threadIdx.x != 0 || blockIdx.x != 0) return;
    long long a[6];
    int b[6];
    bool v64 = true, v32 = true;
    const long long* s64 = (const long long*)seq_raw;
    const long long* r64 = (const long long*)res_raw;
#pragma unroll
    for (int i = 0; i < 3; i++) {
        long long t = s64[i]; a[i] = t;     if (t < 0 || t >= NADJ) v64 = false;
        long long u = r64[i]; a[3 + i] = u; if (u < 0 || u >= NADJ) v64 = false;
        int p = seq_raw[i]; b[i] = p;       if (p < 0 || p >= NADJ) v32 = false;
        int q = res_raw[i]; b[3 + i] = q;   if (q < 0 || q >= NADJ) v32 = false;
    }
    (void)v32;
#pragma unroll
    for (int i = 0; i < NADJ; i++) g_used[i] = 0;
#pragma unroll
    for (int i = 0; i < 6; i++) {
        int v = v64 ? (int)a[i] : b[i];
        g_adj_idx[i] = v;
        g_used[v] = 1;
    }
}

// ---------------- CSR build --------------------------------------------
__global__ void zero_cnt_kernel() {
    int i = blockIdx.x * blockDim.x + threadIdx.x;
    if (i < NADJ * NNODES) g_cnt[i] = 0;
}

__global__ void hist_kernel(const int* __restrict__ rows) {
    int i = blockIdx.x * blockDim.x + threadIdx.x;
    if (i >= NADJ * NEDGE) return;
    int adj = i / NEDGE;
    if (!g_used[adj]) return;
    int r = rows[i];
    atomicAdd(&g_cnt[adj * NNODES + r], 1);
}

__global__ __launch_bounds__(SCAN_B) void scanA_kernel() {
    __shared__ int s[SCAN_B];
    int bx = blockIdx.x;
    int adj = bx / BLK_PER_ADJ;
    int blk = bx % BLK_PER_ADJ;
    int t = threadIdx.x;
    int i = blk * SCAN_B + t;
    int v = (i < NNODES) ? g_cnt[adj * NNODES + i] : 0;
    s[t] = v;
    __syncthreads();
#pragma unroll
    for (int off = 1; off < SCAN_B; off <<= 1) {
        int u = (t >= off) ? s[t - off] : 0;
        __syncthreads();
        s[t] += u;
        __syncthreads();
    }
    if (i < NNODES) g_cnt[adj * NNODES + i] = s[t] - v;
    if (t == SCAN_B - 1) g_blksum[adj * BLK_PER_ADJ + blk] = s[t];
}

__global__ __launch_bounds__(512) void scanB_kernel() {
    __shared__ int sb[NADJ * BLK_PER_ADJ];
    int t = threadIdx.x;
    for (int i = t; i < NADJ * BLK_PER_ADJ; i += blockDim.x) sb[i] = g_blksum[i];
    __syncthreads();
    if (t < NADJ) {
        int run = 0;
        for (int k = 0; k < BLK_PER_ADJ; k++) {
            int v = sb[t * BLK_PER_ADJ + k];
            sb[t * BLK_PER_ADJ + k] = run;
            run += v;
        }
        g_rowptr[t * (NNODES + 1) + NNODES] = run;
    }
    __syncthreads();
    for (int i = t; i < NADJ * BLK_PER_ADJ; i += blockDim.x) g_blksum[i] = sb[i];
}

__global__ __launch_bounds__(SCAN_B) void scanC_kernel() {
    int bx = blockIdx.x;
    int adj = bx / BLK_PER_ADJ;
    int blk = bx % BLK_PER_ADJ;
    int t = threadIdx.x;
    int i = blk * SCAN_B + t;
    if (i >= NNODES) return;
    int val = g_cnt[adj * NNODES + i] + g_blksum[adj * BLK_PER_ADJ + blk];
    g_rowptr[adj * (NNODES + 1) + i] = val;
    g_cur[adj * NNODES + i] = val;
}

__global__ void scatter_kernel(const int* __restrict__ rows,
                               const int* __restrict__ cols,
                               const float* __restrict__ vals) {
    int i = blockIdx.x * blockDim.x + threadIdx.x;
    if (i >= NADJ * NEDGE) return;
    int adj = i / NEDGE;
    if (!g_used[adj]) return;
    int r = rows[i];
    int pos = atomicAdd(&g_cur[adj * NNODES + r], 1);
    g_edge[(size_t)adj * NEDGE + pos] = make_int2(cols[i], __float_as_int(vals[i]));
}

// ---------------- TF32 split tensor-core GEMM, fp16 output ----------------
#define GBM 128
#define GBN 128
#define GBK 16
#define SPAD 20

__device__ __forceinline__ float f2tf32(float x) {
    float r;
    asm("cvt.rna.tf32.f32 %0, %1;" : "=f"(r) : "f"(x));
    return r;
}

__device__ __forceinline__ void mma_tf32(float* d, const float* a, float b0, float b1) {
    asm volatile(
        "mma.sync.aligned.m16n8k8.row.col.f32.tf32.tf32.f32 "
        "{%0,%1,%2,%3}, {%4,%5,%6,%7}, {%8,%9}, {%0,%1,%2,%3};"
        : "+f"(d[0]), "+f"(d[1]), "+f"(d[2]), "+f"(d[3])
        : "r"(__float_as_uint(a[0])), "r"(__float_as_uint(a[1])),
          "r"(__float_as_uint(a[2])), "r"(__float_as_uint(a[3])),
          "r"(__float_as_uint(b0)), "r"(__float_as_uint(b1)));
}

__global__ __launch_bounds__(256) void gemm_tf32_kernel(
    const float* __restrict__ A, const float* __restrict__ W,
    const float* __restrict__ bias, __half* __restrict__ C) {
    __shared__ float As_hi[GBM][SPAD];
    __shared__ float As_lo[GBM][SPAD];
    __shared__ float Bs_hi[GBN][SPAD];
    __shared__ float Bs_lo[GBN][SPAD];

    int t = threadIdx.x;
    int m0 = blockIdx.x * GBM;
    int n0 = blockIdx.y * GBN;
    int ws = t >> 5, lane = t & 31;
    int wm = ws & 3, wn = ws >> 2;
    int g = lane >> 2, t4 = lane & 3;

    float acc[2][8][4];
#pragma unroll
    for (int i = 0; i < 2; i++)
#pragma unroll
        for (int j = 0; j < 8; j++)
#pragma unroll
            for (int q = 0; q < 4; q++) acc[i][j][q] = 0.f;

    for (int k0 = 0; k0 < NH; k0 += GBK) {
#pragma unroll
        for (int L = 0; L < 2; L++) {
            int f = t + L * 256;
            int m = f >> 2, c4 = f & 3;
            int gm = m0 + m;
            float4 v = make_float4(0.f, 0.f, 0.f, 0.f);
            if (gm < NNODES)
                v = *(const float4*)(A + (size_t)gm * NH + k0 + c4 * 4);
            float4 h, l;
            h.x = f2tf32(v.x); l.x = f2tf32(v.x - h.x);
            h.y = f2tf32(v.y); l.y = f2tf32(v.y - h.y);
            h.z = f2tf32(v.z); l.z = f2tf32(v.z - h.z);
            h.w = f2tf32(v.w); l.w = f2tf32(v.w - h.w);
            *(float4*)&As_hi[m][c4 * 4] = h;
            *(float4*)&As_lo[m][c4 * 4] = l;
        }
#pragma unroll
        for (int L = 0; L < 2; L++) {
            int f = t + L * 256;
            int n = f >> 2, c4 = f & 3;
            float4 v = *(const float4*)(W + (size_t)(n0 + n) * NH + k0 + c4 * 4);
            float4 h, l;
            h.x = f2tf32(v.x); l.x = f2tf32(v.x - h.x);
            h.y = f2tf32(v.y); l.y = f2tf32(v.y - h.y);
            h.z = f2tf32(v.z); l.z = f2tf32(v.z - h.z);
            h.w = f2tf32(v.w); l.w = f2tf32(v.w - h.w);
            *(float4*)&Bs_hi[n][c4 * 4] = h;
            *(float4*)&Bs_lo[n][c4 * 4] = l;
        }
        __syncthreads();

#pragma unroll
        for (int k8 = 0; k8 < GBK / 8; k8++) {
            int kb = k8 * 8;
            float ah[2][4], al[2][4];
#pragma unroll
            for (int i = 0; i < 2; i++) {
                int mr = wm * 32 + i * 16;
                ah[i][0] = As_hi[mr + g][kb + t4];
                ah[i][1] = As_hi[mr + g + 8][kb + t4];
                ah[i][2] = As_hi[mr + g][kb + t4 + 4];
                ah[i][3] = As_hi[mr + g + 8][kb + t4 + 4];
                al[i][0] = As_lo[mr + g][kb + t4];
                al[i][1] = As_lo[mr + g + 8][kb + t4];
                al[i][2] = As_lo[mr + g][kb + t4 + 4];
                al[i][3] = As_lo[mr + g + 8][kb + t4 + 4];
            }
#pragma unroll
            for (int j = 0; j < 8; j++) {
                int nb = wn * 64 + j * 8;
                float b0h = Bs_hi[nb + g][kb + t4];
                float b1h = Bs_hi[nb + g][kb + t4 + 4];
                float b0l = Bs_lo[nb + g][kb + t4];
                float b1l = Bs_lo[nb + g][kb + t4 + 4];
#pragma unroll
                for (int i = 0; i < 2; i++) {
                    mma_tf32(acc[i][j], ah[i], b0h, b1h);
                    mma_tf32(acc[i][j], ah[i], b0l, b1l);
                    mma_tf32(acc[i][j], al[i], b0h, b1h);
                }
            }
        }
        __syncthreads();
    }

    // epilogue: + bias, convert to fp16, store half2
#pragma unroll
    for (int j = 0; j < 8; j++) {
        int c = n0 + wn * 64 + j * 8 + 2 * t4;
        float bx = __ldg(bias + c);
        float by = __ldg(bias + c + 1);
#pragma unroll
        for (int i = 0; i < 2; i++) {
            int r0 = m0 + wm * 32 + i * 16 + g;
            if (r0 < NNODES) {
                *(half2*)(C + (size_t)r0 * NH + c) =
                    __floats2half2_rn(acc[i][j][0] + bx, acc[i][j][1] + by);
            }
            int r1 = r0 + 8;
            if (r1 < NNODES) {
                *(half2*)(C + (size_t)r1 * NH + c) =
                    __floats2half2_rn(acc[i][j][2] + bx, acc[i][j][3] + by);
            }
        }
    }
}

// ---------------- CSR SpMM: warp-per-row, fp16 gather, fp32 accum ---------
// Each lane owns 8 consecutive cols (lane*8 .. lane*8+7) = one uint4 of halves.
__device__ __forceinline__ void gather_accum(float* acc, const __half* __restrict__ src,
                                             int c, float v, int lane) {
    const uint4* row = (const uint4*)(src + (size_t)c * NH);
    uint4 pv = __ldg(row + lane);
    const __half2* h = (const __half2*)&pv;
    float2 f0 = __half22float2(h[0]);
    float2 f1 = __half22float2(h[1]);
    float2 f2 = __half22float2(h[2]);
    float2 f3 = __half22float2(h[3]);
    acc[0] += v * f0.x; acc[1] += v * f0.y;
    acc[2] += v * f1.x; acc[3] += v * f1.y;
    acc[4] += v * f2.x; acc[5] += v * f2.y;
    acc[6] += v * f3.x; acc[7] += v * f3.y;
}

template <int NSRC>
__device__ __forceinline__ void spmm_accum(float* acc, int w, int lane,
                                           const __half* __restrict__ s0, int sel0,
                                           const __half* __restrict__ s1, int sel1,
                                           const __half* __restrict__ s2, int sel2) {
    const __half* srcs[3] = {s0, s1, s2};
    const int sels[3] = {sel0, sel1, sel2};
#pragma unroll
    for (int s = 0; s < NSRC; s++) {
        int adj = g_adj_idx[sels[s]];
        const int* rp = g_rowptr + adj * (NNODES + 1);
        int beg = __ldg(rp + w), end = __ldg(rp + w + 1);
        const int2* ed = g_edge + (size_t)adj * NEDGE;
        const __half* src = srcs[s];
        int2 e0 = make_int2(0, 0);
        if (beg < end) e0 = __ldg(ed + beg);
        for (int e = beg; e < end; e++) {
            int2 en = make_int2(0, 0);
            if (e + 1 < end) en = __ldg(ed + e + 1);
            gather_accum(acc, src, e0.x, __int_as_float(e0.y), lane);
            e0 = en;
        }
    }
}

template <int NSRC>
__global__ __launch_bounds__(256) void spmm_kernel(const __half* __restrict__ s0, int sel0,
                                                   const __half* __restrict__ s1, int sel1,
                                                   const __half* __restrict__ s2, int sel2,
                                                   __half* __restrict__ dst) {
    int w = (blockIdx.x * blockDim.x + threadIdx.x) >> 5;
    int lane = threadIdx.x & 31;
    if (w >= NNODES) return;
    float acc[8];
#pragma unroll
    for (int i = 0; i < 8; i++) acc[i] = 0.f;
    spmm_accum<NSRC>(acc, w, lane, s0, sel0, s1, sel1, s2, sel2);
    // pack 8 fp32 -> 4 half2 -> uint4, one 16B store per lane
    uint4 pk;
    half2* ph = (half2*)&pk;
    ph[0] = __floats2half2_rn(acc[0], acc[1]);
    ph[1] = __floats2half2_rn(acc[2], acc[3]);
    ph[2] = __floats2half2_rn(acc[4], acc[5]);
    ph[3] = __floats2half2_rn(acc[6], acc[7]);
    ((uint4*)(dst + (size_t)w * NH))[lane] = pk;
}

// ---------------- fused step-3 SpMM + LayerNorm + exact GELU -------------
__global__ __launch_bounds__(256) void spmm_ln_gelu_kernel(
    const __half* __restrict__ s0, int sel0,
    const __half* __restrict__ s1, int sel1,
    const __half* __restrict__ s2, int sel2,
    const float* __restrict__ gamma, const float* __restrict__ beta,
    float* __restrict__ out) {
    int w = (blockIdx.x * blockDim.x + threadIdx.x) >> 5;
    int lane = threadIdx.x & 31;
    if (w >= NNODES) return;
    float acc[8];
#pragma unroll
    for (int i = 0; i < 8; i++) acc[i] = 0.f;
    spmm_accum<3>(acc, w, lane, s0, sel0, s1, sel1, s2, sel2);

    float sum = 0.f, sq = 0.f;
#pragma unroll
    for (int i = 0; i < 8; i++) { sum += acc[i]; sq += acc[i] * acc[i]; }
#pragma unroll
    for (int off = 16; off >= 1; off >>= 1) {
        sum += __shfl_xor_sync(0xFFFFFFFFu, sum, off);
        sq  += __shfl_xor_sync(0xFFFFFFFFu, sq, off);
    }
    float mean = sum * (1.f / NH);
    float var = sq * (1.f / NH) - mean * mean;
    float inv = rsqrtf(var + LN_EPS);

    // lane owns cols lane*8 .. lane*8+7
    const float4* g4 = (const float4*)gamma;
    const float4* b4 = (const float4*)beta;
    float4 ga = __ldg(g4 + lane * 2), gb = __ldg(g4 + lane * 2 + 1);
    float4 ba = __ldg(b4 + lane * 2), bb = __ldg(b4 + lane * 2 + 1);
    float gs[8] = {ga.x, ga.y, ga.z, ga.w, gb.x, gb.y, gb.z, gb.w};
    float bs[8] = {ba.x, ba.y, ba.z, ba.w, bb.x, bb.y, bb.z, bb.w};
    float r[8];
#pragma unroll
    for (int i = 0; i < 8; i++) {
        float y = (acc[i] - mean) * inv * gs[i] + bs[i];
        r[i] = 0.5f * y * (1.f + erff(y * 0.70710678118654752f));
    }
    float4* o4 = (float4*)(out + (size_t)w * NH);
    o4[lane * 2] = make_float4(r[0], r[1], r[2], r[3]);
    o4[lane * 2 + 1] = make_float4(r[4], r[5], r[6], r[7]);
}

// ---------------- launch ---------------------------------------------
extern "C" void kernel_launch(void* const* d_in, const int* in_sizes, int n_in,
                              void* d_out, int out_size) {
    const float* x    = (const float*)d_in[0];
    const int* rows   = (const int*)d_in[1];
    const int* cols   = (const int*)d_in[2];
    const float* vals = (const float*)d_in[3];
    const int* seqr   = (const int*)d_in[4];
    const int* resr   = (const int*)d_in[5];
    const float* W    = (const float*)d_in[6];
    const float* b    = (const float*)d_in[7];
    const float* gamma = (const float*)d_in[8];
    const float* beta  = (const float*)d_in[9];
    float* out = (float*)d_out;

    static __half *s0p = nullptr, *s1p = nullptr, *s2p = nullptr;
    static cudaStream_t st2;
    static cudaEvent_t evFork, evJoin;
    if (!s0p) {
        cudaGetSymbolAddress((void**)&s0p, g_state0);
        cudaGetSymbolAddress((void**)&s1p, g_state1);
        cudaGetSymbolAddress((void**)&s2p, g_state2);
        cudaStreamCreateWithFlags(&st2, cudaStreamNonBlocking);
        cudaEventCreateWithFlags(&evFork, cudaEventDisableTiming);
        cudaEventCreateWithFlags(&evJoin, cudaEventDisableTiming);
    }

    // fork: GEMM on st2 runs concurrently with the CSR build chain
    cudaEventRecord(evFork, 0);
    cudaStreamWaitEvent(st2, evFork, 0);
    gemm_tf32_kernel<<<dim3((NNODES + GBM - 1) / GBM, NH / GBN), 256, 0, st2>>>(x, W, b, s0p);
    cudaEventRecord(evJoin, st2);

    // CSR build on the main (captured) stream
    decode_idx_kernel<<<1, 1>>>(seqr, resr);
    zero_cnt_kernel<<<(NADJ * NNODES + 255) / 256, 256>>>();
    hist_kernel<<<(NADJ * NEDGE + 255) / 256, 256>>>(rows);
    scanA_kernel<<<NADJ * BLK_PER_ADJ, SCAN_B>>>();
    scanB_kernel<<<1, 512>>>();
    scanC_kernel<<<NADJ * BLK_PER_ADJ, SCAN_B>>>();
    scatter_kernel<<<(NADJ * NEDGE + 255) / 256, 256>>>(rows, cols, vals);

    // join: SpMM chain needs both GEMM output and CSR
    cudaStreamWaitEvent(0, evJoin, 0);

    const int spmm_blocks = (NNODES + 7) / 8;  // warp per row, 8 warps/block
    spmm_kernel<1><<<spmm_blocks, 256>>>(s0p, 0, nullptr, 0, nullptr, 0, s1p);
    spmm_kernel<2><<<spmm_blocks, 256>>>(s1p, 1, s0p, 3, nullptr, 0, s2p);
    spmm_ln_gelu_kernel<<<spmm_blocks, 256>>>(s2p, 2, s0p, 4, s1p, 5, gamma, beta, out);
}

// round 8
// speedup vs baseline: 1.9312x; 1.0003x over previous
#include <cuda_runtime.h>
#include <cuda_fp16.h>
#include <math.h>

#define NNODES 50000
#define NADJ   6
#define NEDGE  800000
#define NH     256
#define LN_EPS 1e-5f

#define SCAN_B 1024
#define BLK_PER_ADJ ((NNODES + SCAN_B - 1) / SCAN_B)   // 49

// ---------------- device scratch (no allocations allowed) ----------------
static __device__ __align__(16) __half g_state0[(size_t)NNODES * NH];
static __device__ __align__(16) __half g_state1[(size_t)NNODES * NH];
static __device__ __align__(16) __half g_state2[(size_t)NNODES * NH];
static __device__ int   g_cnt[NADJ * NNODES];
static __device__ int   g_rowptr[NADJ * (NNODES + 1)];
static __device__ int   g_cur[NADJ * NNODES];
static __device__ int   g_blksum[NADJ * BLK_PER_ADJ];
static __device__ __align__(16) int2 g_edge[(size_t)NADJ * NEDGE];  // {col, val bits}
static __device__ int   g_adj_idx[6];   // [seq0,seq1,seq2,res0,res1,res2]
static __device__ int   g_used[NADJ];

// ---------------- idx decode: int32 vs int64 autodetect -------------------
__global__ void decode_idx_kernel(const int* __restrict__ seq_raw,
                                  const int* __restrict__ res_raw) {
    if (threadIdx.x != 0 || blockIdx.x != 0) return;
    long long a[6];
    int b[6];
    bool v64 = true, v32 = true;
    const long long* s64 = (const long long*)seq_raw;
    const long long* r64 = (const long long*)res_raw;
#pragma unroll
    for (int i = 0; i < 3; i++) {
        long long t = s64[i]; a[i] = t;     if (t < 0 || t >= NADJ) v64 = false;
        long long u = r64[i]; a[3 + i] = u; if (u < 0 || u >= NADJ) v64 = false;
        int p = seq_raw[i]; b[i] = p;       if (p < 0 || p >= NADJ) v32 = false;
        int q = res_raw[i]; b[3 + i] = q;   if (q < 0 || q >= NADJ) v32 = false;
    }
    (void)v32;
#pragma unroll
    for (int i = 0; i < NADJ; i++) g_used[i] = 0;
#pragma unroll
    for (int i = 0; i < 6; i++) {
        int v = v64 ? (int)a[i] : b[i];
        g_adj_idx[i] = v;
        g_used[v] = 1;
    }
}

// ---------------- CSR build --------------------------------------------
__global__ void zero_cnt_kernel() {
    int i = blockIdx.x * blockDim.x + threadIdx.x;
    if (i < NADJ * NNODES) g_cnt[i] = 0;
}

__global__ void hist_kernel(const int* __restrict__ rows) {
    int i = blockIdx.x * blockDim.x + threadIdx.x;
    if (i >= NADJ * NEDGE) return;
    int adj = i / NEDGE;
    if (!g_used[adj]) return;
    int r = rows[i];
    atomicAdd(&g_cnt[adj * NNODES + r], 1);
}

__global__ __launch_bounds__(SCAN_B) void scanA_kernel() {
    __shared__ int s[SCAN_B];
    int bx = blockIdx.x;
    int adj = bx / BLK_PER_ADJ;
    int blk = bx % BLK_PER_ADJ;
    int t = threadIdx.x;
    int i = blk * SCAN_B + t;
    int v = (i < NNODES) ? g_cnt[adj * NNODES + i] : 0;
    s[t] = v;
    __syncthreads();
#pragma unroll
    for (int off = 1; off < SCAN_B; off <<= 1) {
        int u = (t >= off) ? s[t - off] : 0;
        __syncthreads();
        s[t] += u;
        __syncthreads();
    }
    if (i < NNODES) g_cnt[adj * NNODES + i] = s[t] - v;
    if (t == SCAN_B - 1) g_blksum[adj * BLK_PER_ADJ + blk] = s[t];
}

__global__ __launch_bounds__(512) void scanB_kernel() {
    __shared__ int sb[NADJ * BLK_PER_ADJ];
    int t = threadIdx.x;
    for (int i = t; i < NADJ * BLK_PER_ADJ; i += blockDim.x) sb[i] = g_blksum[i];
    __syncthreads();
    if (t < NADJ) {
        int run = 0;
        for (int k = 0; k < BLK_PER_ADJ; k++) {
            int v = sb[t * BLK_PER_ADJ + k];
            sb[t * BLK_PER_ADJ + k] = run;
            run += v;
        }
        g_rowptr[t * (NNODES + 1) + NNODES] = run;
    }
    __syncthreads();
    for (int i = t; i < NADJ * BLK_PER_ADJ; i += blockDim.x) g_blksum[i] = sb[i];
}

__global__ __launch_bounds__(SCAN_B) void scanC_kernel() {
    int bx = blockIdx.x;
    int adj = bx / BLK_PER_ADJ;
    int blk = bx % BLK_PER_ADJ;
    int t = threadIdx.x;
    int i = blk * SCAN_B + t;
    if (i >= NNODES) return;
    int val = g_cnt[adj * NNODES + i] + g_blksum[adj * BLK_PER_ADJ + blk];
    g_rowptr[adj * (NNODES + 1) + i] = val;
    g_cur[adj * NNODES + i] = val;
}

__global__ void scatter_kernel(const int* __restrict__ rows,
                               const int* __restrict__ cols,
                               const float* __restrict__ vals) {
    int i = blockIdx.x * blockDim.x + threadIdx.x;
    if (i >= NADJ * NEDGE) return;
    int adj = i / NEDGE;
    if (!g_used[adj]) return;
    int r = rows[i];
    int pos = atomicAdd(&g_cur[adj * NNODES + r], 1);
    g_edge[(size_t)adj * NEDGE + pos] = make_int2(cols[i], __float_as_int(vals[i]));
}

// ---------------- TF32 split tensor-core GEMM, fp16 output ----------------
#define GBM 128
#define GBN 128
#define GBK 16
#define SPAD 20

__device__ __forceinline__ float f2tf32(float x) {
    float r;
    asm("cvt.rna.tf32.f32 %0, %1;" : "=f"(r) : "f"(x));
    return r;
}

__device__ __forceinline__ void mma_tf32(float* d, const float* a, float b0, float b1) {
    asm volatile(
        "mma.sync.aligned.m16n8k8.row.col.f32.tf32.tf32.f32 "
        "{%0,%1,%2,%3}, {%4,%5,%6,%7}, {%8,%9}, {%0,%1,%2,%3};"
        : "+f"(d[0]), "+f"(d[1]), "+f"(d[2]), "+f"(d[3])
        : "r"(__float_as_uint(a[0])), "r"(__float_as_uint(a[1])),
          "r"(__float_as_uint(a[2])), "r"(__float_as_uint(a[3])),
          "r"(__float_as_uint(b0)), "r"(__float_as_uint(b1)));
}

__global__ __launch_bounds__(256) void gemm_tf32_kernel(
    const float* __restrict__ A, const float* __restrict__ W,
    const float* __restrict__ bias, __half* __restrict__ C) {
    __shared__ float As_hi[GBM][SPAD];
    __shared__ float As_lo[GBM][SPAD];
    __shared__ float Bs_hi[GBN][SPAD];
    __shared__ float Bs_lo[GBN][SPAD];

    int t = threadIdx.x;
    int m0 = blockIdx.x * GBM;
    int n0 = blockIdx.y * GBN;
    int ws = t >> 5, lane = t & 31;
    int wm = ws & 3, wn = ws >> 2;
    int g = lane >> 2, t4 = lane & 3;

    float acc[2][8][4];
#pragma unroll
    for (int i = 0; i < 2; i++)
#pragma unroll
        for (int j = 0; j < 8; j++)
#pragma unroll
            for (int q = 0; q < 4; q++) acc[i][j][q] = 0.f;

    for (int k0 = 0; k0 < NH; k0 += GBK) {
#pragma unroll
        for (int L = 0; L < 2; L++) {
            int f = t + L * 256;
            int m = f >> 2, c4 = f & 3;
            int gm = m0 + m;
            float4 v = make_float4(0.f, 0.f, 0.f, 0.f);
            if (gm < NNODES)
                v = *(const float4*)(A + (size_t)gm * NH + k0 + c4 * 4);
            float4 h, l;
            h.x = f2tf32(v.x); l.x = f2tf32(v.x - h.x);
            h.y = f2tf32(v.y); l.y = f2tf32(v.y - h.y);
            h.z = f2tf32(v.z); l.z = f2tf32(v.z - h.z);
            h.w = f2tf32(v.w); l.w = f2tf32(v.w - h.w);
            *(float4*)&As_hi[m][c4 * 4] = h;
            *(float4*)&As_lo[m][c4 * 4] = l;
        }
#pragma unroll
        for (int L = 0; L < 2; L++) {
            int f = t + L * 256;
            int n = f >> 2, c4 = f & 3;
            float4 v = *(const float4*)(W + (size_t)(n0 + n) * NH + k0 + c4 * 4);
            float4 h, l;
            h.x = f2tf32(v.x); l.x = f2tf32(v.x - h.x);
            h.y = f2tf32(v.y); l.y = f2tf32(v.y - h.y);
            h.z = f2tf32(v.z); l.z = f2tf32(v.z - h.z);
            h.w = f2tf32(v.w); l.w = f2tf32(v.w - h.w);
            *(float4*)&Bs_hi[n][c4 * 4] = h;
            *(float4*)&Bs_lo[n][c4 * 4] = l;
        }
        __syncthreads();

#pragma unroll
        for (int k8 = 0; k8 < GBK / 8; k8++) {
            int kb = k8 * 8;
            float ah[2][4], al[2][4];
#pragma unroll
            for (int i = 0; i < 2; i++) {
                int mr = wm * 32 + i * 16;
                ah[i][0] = As_hi[mr + g][kb + t4];
                ah[i][1] = As_hi[mr + g + 8][kb + t4];
                ah[i][2] = As_hi[mr + g][kb + t4 + 4];
                ah[i][3] = As_hi[mr + g + 8][kb + t4 + 4];
                al[i][0] = As_lo[mr + g][kb + t4];
                al[i][1] = As_lo[mr + g + 8][kb + t4];
                al[i][2] = As_lo[mr + g][kb + t4 + 4];
                al[i][3] = As_lo[mr + g + 8][kb + t4 + 4];
            }
#pragma unroll
            for (int j = 0; j < 8; j++) {
                int nb = wn * 64 + j * 8;
                float b0h = Bs_hi[nb + g][kb + t4];
                float b1h = Bs_hi[nb + g][kb + t4 + 4];
                float b0l = Bs_lo[nb + g][kb + t4];
                float b1l = Bs_lo[nb + g][kb + t4 + 4];
#pragma unroll
                for (int i = 0; i < 2; i++) {
                    mma_tf32(acc[i][j], ah[i], b0h, b1h);
                    mma_tf32(acc[i][j], ah[i], b0l, b1l);
                    mma_tf32(acc[i][j], al[i], b0h, b1h);
                }
            }
        }
        __syncthreads();
    }

    // epilogue: + bias, convert to fp16, store half2
#pragma unroll
    for (int j = 0; j < 8; j++) {
        int c = n0 + wn * 64 + j * 8 + 2 * t4;
        float bx = __ldg(bias + c);
        float by = __ldg(bias + c + 1);
#pragma unroll
        for (int i = 0; i < 2; i++) {
            int r0 = m0 + wm * 32 + i * 16 + g;
            if (r0 < NNODES) {
                *(half2*)(C + (size_t)r0 * NH + c) =
                    __floats2half2_rn(acc[i][j][0] + bx, acc[i][j][1] + by);
            }
            int r1 = r0 + 8;
            if (r1 < NNODES) {
                *(half2*)(C + (size_t)r1 * NH + c) =
                    __floats2half2_rn(acc[i][j][2] + bx, acc[i][j][3] + by);
            }
        }
    }
}

// ---------------- CSR SpMM: warp-per-row, fp16 gather, fp32 accum ---------
// Each lane owns 8 consecutive cols (lane*8 .. lane*8+7) = one uint4 of halves.
__device__ __forceinline__ void gather_accum(float* acc, const __half* __restrict__ src,
                                             int c, float v, int lane) {
    const uint4* row = (const uint4*)(src + (size_t)c * NH);
    uint4 pv = __ldg(row + lane);
    const __half2* h = (const __half2*)&pv;
    float2 f0 = __half22float2(h[0]);
    float2 f1 = __half22float2(h[1]);
    float2 f2 = __half22float2(h[2]);
    float2 f3 = __half22float2(h[3]);
    acc[0] += v * f0.x; acc[1] += v * f0.y;
    acc[2] += v * f1.x; acc[3] += v * f1.y;
    acc[4] += v * f2.x; acc[5] += v * f2.y;
    acc[6] += v * f3.x; acc[7] += v * f3.y;
}

template <int NSRC>
__device__ __forceinline__ void spmm_accum(float* acc, int w, int lane,
                                           const __half* __restrict__ s0, int sel0,
                                           const __half* __restrict__ s1, int sel1,
                                           const __half* __restrict__ s2, int sel2) {
    const __half* srcs[3] = {s0, s1, s2};
    const int sels[3] = {sel0, sel1, sel2};
#pragma unroll
    for (int s = 0; s < NSRC; s++) {
        int adj = g_adj_idx[sels[s]];
        const int* rp = g_rowptr + adj * (NNODES + 1);
        int beg = __ldg(rp + w), end = __ldg(rp + w + 1);
        const int2* ed = g_edge + (size_t)adj * NEDGE;
        const __half* src = srcs[s];
        int2 e0 = make_int2(0, 0);
        if (beg < end) e0 = __ldg(ed + beg);
        for (int e = beg; e < end; e++) {
            int2 en = make_int2(0, 0);
            if (e + 1 < end) en = __ldg(ed + e + 1);
            gather_accum(acc, src, e0.x, __int_as_float(e0.y), lane);
            e0 = en;
        }
    }
}

template <int NSRC>
__global__ __launch_bounds__(256) void spmm_kernel(const __half* __restrict__ s0, int sel0,
                                                   const __half* __restrict__ s1, int sel1,
                                                   const __half* __restrict__ s2, int sel2,
                                                   __half* __restrict__ dst) {
    int w = (blockIdx.x * blockDim.x + threadIdx.x) >> 5;
    int lane = threadIdx.x & 31;
    if (w >= NNODES) return;
    float acc[8];
#pragma unroll
    for (int i = 0; i < 8; i++) acc[i] = 0.f;
    spmm_accum<NSRC>(acc, w, lane, s0, sel0, s1, sel1, s2, sel2);
    // pack 8 fp32 -> 4 half2 -> uint4, one 16B store per lane
    uint4 pk;
    half2* ph = (half2*)&pk;
    ph[0] = __floats2half2_rn(acc[0], acc[1]);
    ph[1] = __floats2half2_rn(acc[2], acc[3]);
    ph[2] = __floats2half2_rn(acc[4], acc[5]);
    ph[3] = __floats2half2_rn(acc[6], acc[7]);
    ((uint4*)(dst + (size_t)w * NH))[lane] = pk;
}

// ---------------- fused step-3 SpMM + LayerNorm + exact GELU -------------
__global__ __launch_bounds__(256) void spmm_ln_gelu_kernel(
    const __half* __restrict__ s0, int sel0,
    const __half* __restrict__ s1, int sel1,
    const __half* __restrict__ s2, int sel2,
    const float* __restrict__ gamma, const float* __restrict__ beta,
    float* __restrict__ out) {
    int w = (blockIdx.x * blockDim.x + threadIdx.x) >> 5;
    int lane = threadIdx.x & 31;
    if (w >= NNODES) return;
    float acc[8];
#pragma unroll
    for (int i = 0; i < 8; i++) acc[i] = 0.f;
    spmm_accum<3>(acc, w, lane, s0, sel0, s1, sel1, s2, sel2);

    float sum = 0.f, sq = 0.f;
#pragma unroll
    for (int i = 0; i < 8; i++) { sum += acc[i]; sq += acc[i] * acc[i]; }
#pragma unroll
    for (int off = 16; off >= 1; off >>= 1) {
        sum += __shfl_xor_sync(0xFFFFFFFFu, sum, off);
        sq  += __shfl_xor_sync(0xFFFFFFFFu, sq, off);
    }
    float mean = sum * (1.f / NH);
    float var = sq * (1.f / NH) - mean * mean;
    float inv = rsqrtf(var + LN_EPS);

    // lane owns cols lane*8 .. lane*8+7
    const float4* g4 = (const float4*)gamma;
    const float4* b4 = (const float4*)beta;
    float4 ga = __ldg(g4 + lane * 2), gb = __ldg(g4 + lane * 2 + 1);
    float4 ba = __ldg(b4 + lane * 2), bb = __ldg(b4 + lane * 2 + 1);
    float gs[8] = {ga.x, ga.y, ga.z, ga.w, gb.x, gb.y, gb.z, gb.w};
    float bs[8] = {ba.x, ba.y, ba.z, ba.w, bb.x, bb.y, bb.z, bb.w};
    float r[8];
#pragma unroll
    for (int i = 0; i < 8; i++) {
        float y = (acc[i] - mean) * inv * gs[i] + bs[i];
        r[i] = 0.5f * y * (1.f + erff(y * 0.70710678118654752f));
    }
    float4* o4 = (float4*)(out + (size_t)w * NH);
    o4[lane * 2] = make_float4(r[0], r[1], r[2], r[3]);
    o4[lane * 2 + 1] = make_float4(r[4], r[5], r[6], r[7]);
}

// ---------------- launch ---------------------------------------------
extern "C" void kernel_launch(void* const* d_in, const int* in_sizes, int n_in,
                              void* d_out, int out_size) {
    const float* x    = (const float*)d_in[0];
    const int* rows   = (const int*)d_in[1];
    const int* cols   = (const int*)d_in[2];
    const float* vals = (const float*)d_in[3];
    const int* seqr   = (const int*)d_in[4];
    const int* resr   = (const int*)d_in[5];
    const float* W    = (const float*)d_in[6];
    const float* b    = (const float*)d_in[7];
    const float* gamma = (const float*)d_in[8];
    const float* beta  = (const float*)d_in[9];
    float* out = (float*)d_out;

    static __half *s0p = nullptr, *s1p = nullptr, *s2p = nullptr;
    static cudaStream_t st2;
    static cudaEvent_t evFork, evJoin;
    if (!s0p) {
        cudaGetSymbolAddress((void**)&s0p, g_state0);
        cudaGetSymbolAddress((void**)&s1p, g_state1);
        cudaGetSymbolAddress((void**)&s2p, g_state2);
        cudaStreamCreateWithFlags(&st2, cudaStreamNonBlocking);
        cudaEventCreateWithFlags(&evFork, cudaEventDisableTiming);
        cudaEventCreateWithFlags(&evJoin, cudaEventDisableTiming);
    }

    // fork: GEMM on st2 runs concurrently with the CSR build chain
    cudaEventRecord(evFork, 0);
    cudaStreamWaitEvent(st2, evFork, 0);
    gemm_tf32_kernel<<<dim3((NNODES + GBM - 1) / GBM, NH / GBN), 256, 0, st2>>>(x, W, b, s0p);
    cudaEventRecord(evJoin, st2);

    // CSR build on the main (captured) stream
    decode_idx_kernel<<<1, 1>>>(seqr, resr);
    zero_cnt_kernel<<<(NADJ * NNODES + 255) / 256, 256>>>();
    hist_kernel<<<(NADJ * NEDGE + 255) / 256, 256>>>(rows);
    scanA_kernel<<<NADJ * BLK_PER_ADJ, SCAN_B>>>();
    scanB_kernel<<<1, 512>>>();
    scanC_kernel<<<NADJ * BLK_PER_ADJ, SCAN_B>>>();
    scatter_kernel<<<(NADJ * NEDGE + 255) / 256, 256>>>(rows, cols, vals);

    // join: SpMM chain needs both GEMM output and CSR
    cudaStreamWaitEvent(0, evJoin, 0);

    const int spmm_blocks = (NNODES + 7) / 8;  // warp per row, 8 warps/block
    spmm_kernel<1><<<spmm_blocks, 256>>>(s0p, 0, nullptr, 0, nullptr, 0, s1p);
    spmm_kernel<2><<<spmm_blocks, 256>>>(s1p, 1, s0p, 3, nullptr, 0, s2p);
    spmm_ln_gelu_kernel<<<spmm_blocks, 256>>>(s2p, 2, s0p, 4, s1p, 5, gamma, beta, out);
}